// round 1
// baseline (speedup 1.0000x reference)
#include <cuda_runtime.h>

#define D   384
#define DP  388            // padded smem row stride (words), 388 mod 32 = 4
#define BTOT 16
#define TTOT 2048

// Scratch for Q, K, V projections (static __device__ — no allocation).
__device__ float g_Q[BTOT * TTOT * D];
__device__ float g_K[BTOT * TTOT * D];
__device__ float g_V[BTOT * TTOT * D];

// ---------------------------------------------------------------------------
// Projection GEMM: Y[m][n] = X[m][k] * W[k][n], M=32768, N=384, K=384.
// 128x128 CTA tile, BK=8, 256 threads, 8x8 per-thread microtile.
// blockIdx.z selects which of Wq/Wk/Wv (and g_Q/g_K/g_V) this CTA computes.
// ---------------------------------------------------------------------------
__global__ void __launch_bounds__(256, 2) proj_kernel(const float* __restrict__ X,
                                                      const float* __restrict__ W0,
                                                      const float* __restrict__ W1,
                                                      const float* __restrict__ W2) {
    __shared__ float sA[8][132];   // padded: store conflict-free, read broadcast
    __shared__ float sB[8][132];

    const float* W = (blockIdx.z == 0) ? W0 : ((blockIdx.z == 1) ? W1 : W2);
    float* Y       = (blockIdx.z == 0) ? g_Q : ((blockIdx.z == 1) ? g_K : g_V);

    const int mt  = blockIdx.y * 128;
    const int nt  = blockIdx.x * 128;
    const int tid = threadIdx.x;
    const int tx  = tid & 15;       // 16 col groups of 8
    const int ty  = tid >> 4;       // 16 row groups of 8

    float acc[8][8];
#pragma unroll
    for (int i = 0; i < 8; i++)
#pragma unroll
        for (int j = 0; j < 8; j++) acc[i][j] = 0.f;

    for (int k0 = 0; k0 < 384; k0 += 8) {
        __syncthreads();
        // A tile: 128 rows x 8 k, stored transposed sA[k][m]
#pragma unroll
        for (int i = 0; i < 4; i++) {
            int lin = tid + 256 * i;
            int m = lin >> 3, kk = lin & 7;
            sA[kk][m] = X[(size_t)(mt + m) * 384 + k0 + kk];
        }
        // B tile: 8 k x 128 n
#pragma unroll
        for (int i = 0; i < 4; i++) {
            int lin = tid + 256 * i;
            int kk = lin >> 7, n = lin & 127;
            sB[kk][n] = W[(size_t)(k0 + kk) * 384 + nt + n];
        }
        __syncthreads();
#pragma unroll
        for (int kk = 0; kk < 8; kk++) {
            float a[8], b[8];
            *(float4*)&a[0] = *(const float4*)&sA[kk][ty * 8];
            *(float4*)&a[4] = *(const float4*)&sA[kk][ty * 8 + 4];
            *(float4*)&b[0] = *(const float4*)&sB[kk][tx * 8];
            *(float4*)&b[4] = *(const float4*)&sB[kk][tx * 8 + 4];
#pragma unroll
            for (int i = 0; i < 8; i++)
#pragma unroll
                for (int j = 0; j < 8; j++) acc[i][j] += a[i] * b[j];
        }
    }

#pragma unroll
    for (int i = 0; i < 8; i++) {
        float* yr = &Y[(size_t)(mt + ty * 8 + i) * 384 + nt + tx * 8];
        *(float4*)&yr[0] = make_float4(acc[i][0], acc[i][1], acc[i][2], acc[i][3]);
        *(float4*)&yr[4] = make_float4(acc[i][4], acc[i][5], acc[i][6], acc[i][7]);
    }
}

// ---------------------------------------------------------------------------
// Flash attention (causal, online softmax), fp32.
// CTA = (batch b, query tile of 64 rows), 256 threads.
// smem: sQ[64][388] + sK[32][388] + sV[32][388] + sS[64][33] = 207,104 B.
//
// QK^T phase mapping : thread -> (rblk = tid&15, cpair = tid>>4);
//   owns rows {rblk + 16*i, i=0..3} x cols {2*cpair, 2*cpair+1}.
//   Row interleave by 16 + stride-388 padding => conflict-free LDS.128 on Q.
// Softmax/PV mapping : thread -> (row = tid&63, hbase = (tid>>6)*96);
//   4 threads per row each track identical (m, l) in registers (deterministic,
//   no cross-thread reduction); V loads are warp-uniform broadcasts.
// ---------------------------------------------------------------------------
__global__ void __launch_bounds__(256, 1) flash_kernel(float* __restrict__ out) {
    extern __shared__ float sm[];
    float* sQ = sm;                       // 64*388
    float* sK = sQ + 64 * DP;             // 32*388
    float* sV = sK + 32 * DP;             // 32*388
    float* sS = sV + 32 * DP;             // 64*33

    const int b   = blockIdx.y;
    const int qt  = (int)gridDim.x - 1 - (int)blockIdx.x;  // big tiles first
    const int tid = threadIdx.x;

    // Load Q tile (64 x 384) once.
    const float4* Qb = (const float4*)(g_Q + ((size_t)b * TTOT + (size_t)qt * 64) * D);
#pragma unroll
    for (int i = 0; i < 24; i++) {
        int lin = tid + 256 * i;          // 0..6143 float4s
        int r = lin / 96, c4 = lin % 96;
        *(float4*)&sQ[r * DP + c4 * 4] = Qb[lin];
    }

    float Oa[96];
#pragma unroll
    for (int h = 0; h < 96; h++) Oa[h] = 0.f;
    float mrow = -1e30f, lrow = 0.f;

    const int row  = tid & 63;
    const int hb   = (tid >> 6) * 96;
    const int rblk = tid & 15;
    const int c0   = (tid >> 4) * 2;

    const int nkt = qt * 2 + 2;           // causal: only tiles with kg <= qg_max
    const float scale = 0.051031036307982884f;   // 384^-0.5
    const int qg0 = qt * 64;

    for (int jt = 0; jt < nkt; jt++) {
        __syncthreads();                  // prev tile's sS/sV consumers done
        const float4* Kb = (const float4*)(g_K + ((size_t)b * TTOT + (size_t)jt * 32) * D);
        const float4* Vb = (const float4*)(g_V + ((size_t)b * TTOT + (size_t)jt * 32) * D);
#pragma unroll
        for (int i = 0; i < 12; i++) {
            int lin = tid + 256 * i;      // 0..3071 float4s
            int r = lin / 96, c4 = lin % 96;
            *(float4*)&sK[r * DP + c4 * 4] = Kb[lin];
            *(float4*)&sV[r * DP + c4 * 4] = Vb[lin];
        }
        __syncthreads();

        // ---- S = Q K^T (64x32, K-dim 384) ----
        float acc[4][2];
#pragma unroll
        for (int i = 0; i < 4; i++) { acc[i][0] = 0.f; acc[i][1] = 0.f; }
        const float* kp0 = &sK[c0 * DP];
        const float* kp1 = &sK[(c0 + 1) * DP];
#pragma unroll 4
        for (int k = 0; k < 384; k += 4) {
            float4 k0v = *(const float4*)&kp0[k];
            float4 k1v = *(const float4*)&kp1[k];
#pragma unroll
            for (int i = 0; i < 4; i++) {
                float4 qv = *(const float4*)&sQ[(rblk + 16 * i) * DP + k];
                acc[i][0] += qv.x * k0v.x; acc[i][0] += qv.y * k0v.y;
                acc[i][0] += qv.z * k0v.z; acc[i][0] += qv.w * k0v.w;
                acc[i][1] += qv.x * k1v.x; acc[i][1] += qv.y * k1v.y;
                acc[i][1] += qv.z * k1v.z; acc[i][1] += qv.w * k1v.w;
            }
        }
        const int kg0 = jt * 32;
#pragma unroll
        for (int i = 0; i < 4; i++) {
            int r = rblk + 16 * i;
#pragma unroll
            for (int j = 0; j < 2; j++) {
                float s = acc[i][j] * scale;
                if (kg0 + c0 + j > qg0 + r) s = -1e30f;   // causal mask
                sS[r * 33 + c0 + j] = s;
            }
        }
        __syncthreads();

        // ---- online softmax + O += P V ----
        float mtile = -1e30f;
#pragma unroll
        for (int c = 0; c < 32; c++) mtile = fmaxf(mtile, sS[row * 33 + c]);
        float mnew = fmaxf(mrow, mtile);
        float corr = __expf(mrow - mnew);
        mrow = mnew;
#pragma unroll
        for (int h = 0; h < 96; h++) Oa[h] *= corr;
        float rs = 0.f;
        for (int c = 0; c < 32; c++) {
            float pc = __expf(sS[row * 33 + c] - mnew);
            rs += pc;
            const float* vr = &sV[c * DP + hb];
#pragma unroll
            for (int h = 0; h < 96; h += 4) {
                float4 vv = *(const float4*)&vr[h];
                Oa[h]     += pc * vv.x;
                Oa[h + 1] += pc * vv.y;
                Oa[h + 2] += pc * vv.z;
                Oa[h + 3] += pc * vv.w;
            }
        }
        lrow = lrow * corr + rs;
    }

    const float inv = 1.f / lrow;
    float* ob = out + ((size_t)b * TTOT + (size_t)qt * 64 + row) * D + hb;
#pragma unroll
    for (int h = 0; h < 96; h += 4) {
        *(float4*)&ob[h] = make_float4(Oa[h] * inv, Oa[h + 1] * inv,
                                       Oa[h + 2] * inv, Oa[h + 3] * inv);
    }
}

// ---------------------------------------------------------------------------
extern "C" void kernel_launch(void* const* d_in, const int* in_sizes, int n_in,
                              void* d_out, int out_size) {
    const float* x  = (const float*)d_in[0];
    const float* Wq = (const float*)d_in[1];
    const float* Wk = (const float*)d_in[2];
    const float* Wv = (const float*)d_in[3];
    float* out = (float*)d_out;
    (void)in_sizes; (void)n_in; (void)out_size;

    // Q/K/V projections
    dim3 pg(3, 256, 3);   // (N tiles, M tiles, {q,k,v})
    proj_kernel<<<pg, 256>>>(x, Wq, Wk, Wv);

    // Flash attention
    const size_t smem = (size_t)(64 * DP + 32 * DP + 32 * DP + 64 * 33) * sizeof(float); // 207,104 B
    cudaFuncSetAttribute(flash_kernel, cudaFuncAttributeMaxDynamicSharedMemorySize, (int)smem);
    dim3 fg(32, 16);      // (query tiles, batch)
    flash_kernel<<<fg, 256, smem>>>(out);
}

// round 2
// speedup vs baseline: 1.0569x; 1.0569x over previous
#include <cuda_runtime.h>

#define D   384
#define DP  388            // padded smem row stride (words), 388 mod 32 = 4
#define BTOT 16
#define TTOT 2048

// Scratch for Q, K, V projections (static __device__ — no allocation).
__device__ float g_Q[BTOT * TTOT * D];
__device__ float g_K[BTOT * TTOT * D];
__device__ float g_V[BTOT * TTOT * D];

// ---------------------------------------------------------------------------
// Projection GEMM: Y[m][n] = X[m][k] * W[k][n], M=32768, N=384, K=384.
// 128x128 CTA tile, BK=8, 256 threads, 8x8 per-thread microtile.
// blockIdx.z selects which of Wq/Wk/Wv (and g_Q/g_K/g_V) this CTA computes.
// ---------------------------------------------------------------------------
__global__ void __launch_bounds__(256, 2) proj_kernel(const float* __restrict__ X,
                                                      const float* __restrict__ W0,
                                                      const float* __restrict__ W1,
                                                      const float* __restrict__ W2) {
    __shared__ float sA[8][132];   // padded: store conflict-free, read broadcast
    __shared__ float sB[8][132];

    const float* W = (blockIdx.z == 0) ? W0 : ((blockIdx.z == 1) ? W1 : W2);
    float* Y       = (blockIdx.z == 0) ? g_Q : ((blockIdx.z == 1) ? g_K : g_V);

    const int mt  = blockIdx.y * 128;
    const int nt  = blockIdx.x * 128;
    const int tid = threadIdx.x;
    const int tx  = tid & 15;       // 16 col groups of 8
    const int ty  = tid >> 4;       // 16 row groups of 8

    float acc[8][8];
#pragma unroll
    for (int i = 0; i < 8; i++)
#pragma unroll
        for (int j = 0; j < 8; j++) acc[i][j] = 0.f;

    for (int k0 = 0; k0 < 384; k0 += 8) {
        __syncthreads();
        // A tile: 128 rows x 8 k, stored transposed sA[k][m]
#pragma unroll
        for (int i = 0; i < 4; i++) {
            int lin = tid + 256 * i;
            int m = lin >> 3, kk = lin & 7;
            sA[kk][m] = X[(size_t)(mt + m) * 384 + k0 + kk];
        }
        // B tile: 8 k x 128 n
#pragma unroll
        for (int i = 0; i < 4; i++) {
            int lin = tid + 256 * i;
            int kk = lin >> 7, n = lin & 127;
            sB[kk][n] = W[(size_t)(k0 + kk) * 384 + nt + n];
        }
        __syncthreads();
#pragma unroll
        for (int kk = 0; kk < 8; kk++) {
            float a[8], b[8];
            *(float4*)&a[0] = *(const float4*)&sA[kk][ty * 8];
            *(float4*)&a[4] = *(const float4*)&sA[kk][ty * 8 + 4];
            *(float4*)&b[0] = *(const float4*)&sB[kk][tx * 8];
            *(float4*)&b[4] = *(const float4*)&sB[kk][tx * 8 + 4];
#pragma unroll
            for (int i = 0; i < 8; i++)
#pragma unroll
                for (int j = 0; j < 8; j++) acc[i][j] += a[i] * b[j];
        }
    }

#pragma unroll
    for (int i = 0; i < 8; i++) {
        float* yr = &Y[(size_t)(mt + ty * 8 + i) * 384 + nt + tx * 8];
        *(float4*)&yr[0] = make_float4(acc[i][0], acc[i][1], acc[i][2], acc[i][3]);
        *(float4*)&yr[4] = make_float4(acc[i][4], acc[i][5], acc[i][6], acc[i][7]);
    }
}

// ---------------------------------------------------------------------------
// Flash attention (causal, online softmax), fp32.
// CTA = (batch b, query tile of 64 rows), 256 threads.
// smem: sQ[64][388] + sK[32][388] + sV[32][388] + sS[64][33] = 207,104 B.
//
// QK^T phase mapping : thread -> (rblk = tid&15, cpair = tid>>4);
//   owns rows {rblk + 16*i, i=0..3} x cols {2*cpair, 2*cpair+1}.
//   Row interleave by 16 + stride-388 padding => conflict-free LDS.128 on Q.
// Softmax/PV mapping : thread -> (row = tid&63, hbase = (tid>>6)*96);
//   4 threads per row each track identical (m, l) in registers (deterministic,
//   no cross-thread reduction); V loads are warp-uniform broadcasts.
// ---------------------------------------------------------------------------
__global__ void __launch_bounds__(256, 1) flash_kernel(float* __restrict__ out) {
    extern __shared__ float sm[];
    float* sQ = sm;                       // 64*388
    float* sK = sQ + 64 * DP;             // 32*388
    float* sV = sK + 32 * DP;             // 32*388
    float* sS = sV + 32 * DP;             // 64*33

    const int b   = blockIdx.y;
    const int qt  = (int)gridDim.x - 1 - (int)blockIdx.x;  // big tiles first
    const int tid = threadIdx.x;

    // Load Q tile (64 x 384) once.
    const float4* Qb = (const float4*)(g_Q + ((size_t)b * TTOT + (size_t)qt * 64) * D);
#pragma unroll
    for (int i = 0; i < 24; i++) {
        int lin = tid + 256 * i;          // 0..6143 float4s
        int r = lin / 96, c4 = lin % 96;
        *(float4*)&sQ[r * DP + c4 * 4] = Qb[lin];
    }

    float Oa[96];
#pragma unroll
    for (int h = 0; h < 96; h++) Oa[h] = 0.f;
    float mrow = -1e30f, lrow = 0.f;

    const int row  = tid & 63;
    const int hb   = (tid >> 6) * 96;
    const int rblk = tid & 15;
    const int c0   = (tid >> 4) * 2;

    const int nkt = qt * 2 + 2;           // causal: only tiles with kg <= qg_max
    const float scale = 0.051031036307982884f;   // 384^-0.5
    const int qg0 = qt * 64;

    for (int jt = 0; jt < nkt; jt++) {
        __syncthreads();                  // prev tile's sS/sV consumers done
        const float4* Kb = (const float4*)(g_K + ((size_t)b * TTOT + (size_t)jt * 32) * D);
        const float4* Vb = (const float4*)(g_V + ((size_t)b * TTOT + (size_t)jt * 32) * D);
#pragma unroll
        for (int i = 0; i < 12; i++) {
            int lin = tid + 256 * i;      // 0..3071 float4s
            int r = lin / 96, c4 = lin % 96;
            *(float4*)&sK[r * DP + c4 * 4] = Kb[lin];
            *(float4*)&sV[r * DP + c4 * 4] = Vb[lin];
        }
        __syncthreads();

        // ---- S = Q K^T (64x32, K-dim 384) ----
        float acc[4][2];
#pragma unroll
        for (int i = 0; i < 4; i++) { acc[i][0] = 0.f; acc[i][1] = 0.f; }
        const float* kp0 = &sK[c0 * DP];
        const float* kp1 = &sK[(c0 + 1) * DP];
#pragma unroll 4
        for (int k = 0; k < 384; k += 4) {
            float4 k0v = *(const float4*)&kp0[k];
            float4 k1v = *(const float4*)&kp1[k];
#pragma unroll
            for (int i = 0; i < 4; i++) {
                float4 qv = *(const float4*)&sQ[(rblk + 16 * i) * DP + k];
                acc[i][0] += qv.x * k0v.x; acc[i][0] += qv.y * k0v.y;
                acc[i][0] += qv.z * k0v.z; acc[i][0] += qv.w * k0v.w;
                acc[i][1] += qv.x * k1v.x; acc[i][1] += qv.y * k1v.y;
                acc[i][1] += qv.z * k1v.z; acc[i][1] += qv.w * k1v.w;
            }
        }
        const int kg0 = jt * 32;
#pragma unroll
        for (int i = 0; i < 4; i++) {
            int r = rblk + 16 * i;
#pragma unroll
            for (int j = 0; j < 2; j++) {
                float s = acc[i][j] * scale;
                if (kg0 + c0 + j > qg0 + r) s = -1e30f;   // causal mask
                sS[r * 33 + c0 + j] = s;
            }
        }
        __syncthreads();

        // ---- online softmax + O += P V ----
        float mtile = -1e30f;
#pragma unroll
        for (int c = 0; c < 32; c++) mtile = fmaxf(mtile, sS[row * 33 + c]);
        float mnew = fmaxf(mrow, mtile);
        float corr = __expf(mrow - mnew);
        mrow = mnew;
#pragma unroll
        for (int h = 0; h < 96; h++) Oa[h] *= corr;
        float rs = 0.f;
        for (int c = 0; c < 32; c++) {
            float pc = __expf(sS[row * 33 + c] - mnew);
            rs += pc;
            const float* vr = &sV[c * DP + hb];
#pragma unroll
            for (int h = 0; h < 96; h += 4) {
                float4 vv = *(const float4*)&vr[h];
                Oa[h]     += pc * vv.x;
                Oa[h + 1] += pc * vv.y;
                Oa[h + 2] += pc * vv.z;
                Oa[h + 3] += pc * vv.w;
            }
        }
        lrow = lrow * corr + rs;
    }

    const float inv = 1.f / lrow;
    float* ob = out + ((size_t)b * TTOT + (size_t)qt * 64 + row) * D + hb;
#pragma unroll
    for (int h = 0; h < 96; h += 4) {
        *(float4*)&ob[h] = make_float4(Oa[h] * inv, Oa[h + 1] * inv,
                                       Oa[h + 2] * inv, Oa[h + 3] * inv);
    }
}

// ---------------------------------------------------------------------------
extern "C" void kernel_launch(void* const* d_in, const int* in_sizes, int n_in,
                              void* d_out, int out_size) {
    const float* x  = (const float*)d_in[0];
    const float* Wq = (const float*)d_in[1];
    const float* Wk = (const float*)d_in[2];
    const float* Wv = (const float*)d_in[3];
    float* out = (float*)d_out;
    (void)in_sizes; (void)n_in; (void)out_size;

    // Q/K/V projections
    dim3 pg(3, 256, 3);   // (N tiles, M tiles, {q,k,v})
    proj_kernel<<<pg, 256>>>(x, Wq, Wk, Wv);

    // Flash attention
    const size_t smem = (size_t)(64 * DP + 32 * DP + 32 * DP + 64 * 33) * sizeof(float); // 207,104 B
    cudaFuncSetAttribute(flash_kernel, cudaFuncAttributeMaxDynamicSharedMemorySize, (int)smem);
    dim3 fg(32, 16);      // (query tiles, batch)
    flash_kernel<<<fg, 256, smem>>>(out);
}

// round 4
// speedup vs baseline: 3.7497x; 3.5478x over previous
#include <cuda_runtime.h>
#include <cuda_bf16.h>
#include <cstdint>

#define SCALE 0.05103103630798288f   // 384^-0.5
#define SMEM_SZ 81920                 // 2 buffers * 4 arrays * 128*40*2B

__device__ float g_Q [16 * 2048 * 384];
__device__ float g_K [16 * 2048 * 384];
__device__ float g_VT[16 * 384 * 2048];
__device__ float g_WT[3 * 384 * 384];
__device__ float g_S [16ll * 2048 * 2048];

__device__ __forceinline__ uint32_t smem_u32(const void* p) {
    uint32_t a;
    asm("{ .reg .u64 t; cvta.to.shared.u64 t, %1; cvt.u32.u64 %0, t; }" : "=r"(a) : "l"(p));
    return a;
}
__device__ __forceinline__ void ldsm4(uint32_t addr, uint32_t& r0, uint32_t& r1,
                                      uint32_t& r2, uint32_t& r3) {
    asm volatile("ldmatrix.sync.aligned.m8n8.x4.shared.b16 {%0,%1,%2,%3}, [%4];"
        : "=r"(r0), "=r"(r1), "=r"(r2), "=r"(r3) : "r"(addr));
}
__device__ __forceinline__ void mma16816(float* c, uint32_t a0, uint32_t a1, uint32_t a2,
                                         uint32_t a3, uint32_t b0, uint32_t b1) {
    asm volatile("mma.sync.aligned.m16n8k16.row.col.f32.bf16.bf16.f32 "
        "{%0,%1,%2,%3}, {%4,%5,%6,%7}, {%8,%9}, {%0,%1,%2,%3};"
        : "+f"(c[0]), "+f"(c[1]), "+f"(c[2]), "+f"(c[3])
        : "r"(a0), "r"(a1), "r"(a2), "r"(a3), "r"(b0), "r"(b1));
}

// smem buffer layout (bytes, per buffer of 40960): Ah@0, Al@10240, Bh@20480, Bl@30720
// each array: 128 rows x 40 bf16 (stride 80B, 16B-multiple, ldmatrix conflict-free)
struct __align__(8) bpair { __nv_bfloat162 a, b; };
struct LoadRegs { float4 va[4]; float4 vb[4]; };

__device__ __forceinline__ void ld_gmem(LoadRegs& r, const float* __restrict__ gA, int lda,
                                        const float* __restrict__ gB, int ldb, int tid) {
#pragma unroll
    for (int i = 0; i < 4; i++) {
        int lin = tid + 256 * i;                 // 1024 float4 = 128 rows x 32 cols
        int row = lin >> 3, c4 = (lin & 7) * 4;
        r.va[i] = *(const float4*)(gA + (size_t)row * lda + c4);
        r.vb[i] = *(const float4*)(gB + (size_t)row * ldb + c4);
    }
}
__device__ __forceinline__ void split_store(char* hi, char* lo, float4 v, int off) {
    __nv_bfloat162 h0 = __floats2bfloat162_rn(v.x, v.y);
    __nv_bfloat162 h1 = __floats2bfloat162_rn(v.z, v.w);
    float2 f0 = __bfloat1622float2(h0), f1 = __bfloat1622float2(h1);
    bpair hp{h0, h1};
    bpair lp{__floats2bfloat162_rn(v.x - f0.x, v.y - f0.y),
             __floats2bfloat162_rn(v.z - f1.x, v.w - f1.y)};
    *(bpair*)(hi + off) = hp;
    *(bpair*)(lo + off) = lp;
}
__device__ __forceinline__ void st_smem(const LoadRegs& r, char* sbuf, int tid) {
#pragma unroll
    for (int i = 0; i < 4; i++) {
        int lin = tid + 256 * i;
        int row = lin >> 3, c4 = (lin & 7) * 4;
        int off = row * 80 + c4 * 2;
        split_store(sbuf,         sbuf + 10240, r.va[i], off);
        split_store(sbuf + 20480, sbuf + 30720, r.vb[i], off);
    }
}

// one K=32 chunk: 3 split passes x 2 k-steps x (6 ldmatrix.x4 + 16 mma)
__device__ __forceinline__ void compute_chunk(uint32_t sbase, int wm, int wn, int lane,
                                              float acc[2][8][4]) {
    uint32_t aRow0 = (uint32_t)((wm * 32 + (lane & 15)) * 80 + (lane >> 4) * 16);
    uint32_t bRow0 = (uint32_t)((wn * 64 + ((lane >> 4) & 1) * 8 + (lane & 7)) * 80 +
                                ((lane >> 3) & 1) * 16);
#pragma unroll
    for (int pass = 0; pass < 3; pass++) {
        uint32_t abase = sbase + (pass == 2 ? 10240u : 0u) + aRow0;
        uint32_t bbase = sbase + (pass == 1 ? 30720u : 20480u) + bRow0;
#pragma unroll
        for (int ks = 0; ks < 2; ks++) {
            uint32_t a[2][4];
#pragma unroll
            for (int mf = 0; mf < 2; mf++)
                ldsm4(abase + (uint32_t)(mf * 16 * 80 + ks * 32),
                      a[mf][0], a[mf][1], a[mf][2], a[mf][3]);
            uint32_t b[8][2];
#pragma unroll
            for (int nf2 = 0; nf2 < 4; nf2++) {
                uint32_t r0, r1, r2, r3;
                ldsm4(bbase + (uint32_t)(nf2 * 16 * 80 + ks * 32), r0, r1, r2, r3);
                b[nf2 * 2][0] = r0; b[nf2 * 2][1] = r1;
                b[nf2 * 2 + 1][0] = r2; b[nf2 * 2 + 1][1] = r3;
            }
#pragma unroll
            for (int mf = 0; mf < 2; mf++)
#pragma unroll
                for (int nf = 0; nf < 8; nf++)
                    mma16816(acc[mf][nf], a[mf][0], a[mf][1], a[mf][2], a[mf][3],
                             b[nf][0], b[nf][1]);
        }
    }
}

__device__ __forceinline__ void run_gemm(char* smem, int tid,
                                         const float* __restrict__ gA, int lda,
                                         const float* __restrict__ gB, int ldb,
                                         int nch, float acc[2][8][4]) {
    int lane = tid & 31, wid = tid >> 5, wm = wid & 3, wn = wid >> 2;
    uint32_t sb = smem_u32(smem);
    LoadRegs r;
    ld_gmem(r, gA, lda, gB, ldb, tid);
    st_smem(r, smem, tid);
    __syncthreads();
    for (int c = 0; c < nch; c++) {
        bool more = (c + 1 < nch);
        if (more) ld_gmem(r, gA + (size_t)(c + 1) * 32, lda, gB + (size_t)(c + 1) * 32, ldb, tid);
        compute_chunk(sb + (uint32_t)(c & 1) * 40960u, wm, wn, lane, acc);
        if (more) st_smem(r, smem + (size_t)((c + 1) & 1) * 40960, tid);
        __syncthreads();
    }
}

#define ACC_DECL()                              \
    float acc[2][8][4];                         \
    _Pragma("unroll") for (int i = 0; i < 2; i++) \
    _Pragma("unroll") for (int j = 0; j < 8; j++) \
    _Pragma("unroll") for (int q = 0; q < 4; q++) acc[i][j][q] = 0.f;

// acc -> row-major fp32 store, float2 per (mf,h,nf)
__device__ __forceinline__ void epi_rows(float acc[2][8][4], float* __restrict__ Y,
                                         int stride, int tid) {
    int lane = tid & 31, wid = tid >> 5, wm = wid & 3, wn = wid >> 2;
#pragma unroll
    for (int mf = 0; mf < 2; mf++)
#pragma unroll
        for (int h = 0; h < 2; h++) {
            int row = wm * 32 + mf * 16 + (lane >> 2) + h * 8;
#pragma unroll
            for (int nf = 0; nf < 8; nf++) {
                float2 v = make_float2(acc[mf][nf][h * 2], acc[mf][nf][h * 2 + 1]);
                *(float2*)&Y[(size_t)row * stride + wn * 64 + nf * 8 + (lane & 3) * 2] = v;
            }
        }
}

__global__ void wt_kernel(const float* __restrict__ Wq, const float* __restrict__ Wk,
                          const float* __restrict__ Wv) {
    const float* W = (blockIdx.x == 0) ? Wq : ((blockIdx.x == 1) ? Wk : Wv);
    float* O = g_WT + (size_t)blockIdx.x * 384 * 384;
    int base = blockIdx.y * 2304;
    for (int i = base + threadIdx.x; i < base + 2304; i += 256) {
        int n = i / 384, k = i - n * 384;
        O[(size_t)n * 384 + k] = W[(size_t)k * 384 + n];
    }
}

__global__ void __launch_bounds__(256, 1) proj_kernel(const float* __restrict__ X) {
    extern __shared__ char smem[];
    int tid = threadIdx.x;
    int nt = blockIdx.x * 128, mt = blockIdx.y * 128, z = blockIdx.z;
    ACC_DECL();
    run_gemm(smem, tid, X + (size_t)mt * 384, 384,
             g_WT + (size_t)z * 384 * 384 + (size_t)nt * 384, 384, 12, acc);
    if (z == 2) {   // V written transposed: VT[b][d][t]
        int lane = tid & 31, wid = tid >> 5, wm = wid & 3, wn = wid >> 2;
#pragma unroll
        for (int mf = 0; mf < 2; mf++)
#pragma unroll
            for (int h = 0; h < 2; h++) {
                int trow = mt + wm * 32 + mf * 16 + (lane >> 2) + h * 8;
                float* vb = g_VT + (size_t)(trow >> 11) * 384 * 2048 + (trow & 2047);
#pragma unroll
                for (int nf = 0; nf < 8; nf++) {
                    int d0 = nt + wn * 64 + nf * 8 + (lane & 3) * 2;
                    vb[(size_t)d0 * 2048]       = acc[mf][nf][h * 2];
                    vb[(size_t)(d0 + 1) * 2048] = acc[mf][nf][h * 2 + 1];
                }
            }
    } else {
        epi_rows(acc, ((z == 0) ? g_Q : g_K) + (size_t)mt * 384 + nt, 384, tid);
    }
}

__global__ void __launch_bounds__(256, 1) qk_kernel() {
    extern __shared__ char smem[];
    int tid = threadIdx.x;
    int b = blockIdx.y, r_ = blockIdx.x, qt = 0;
    while (r_ > qt) { r_ -= (qt + 1); qt++; }
    int kt = r_;
    ACC_DECL();
    run_gemm(smem, tid, g_Q + ((size_t)b * 2048 + qt * 128) * 384, 384,
             g_K + ((size_t)b * 2048 + kt * 128) * 384, 384, 12, acc);
    int lane = tid & 31, wid = tid >> 5, wm = wid & 3, wn = wid >> 2;
    float* Srow = g_S + ((size_t)b * 2048 + qt * 128) * 2048 + (size_t)kt * 128;
#pragma unroll
    for (int mf = 0; mf < 2; mf++)
#pragma unroll
        for (int h = 0; h < 2; h++) {
            int row = wm * 32 + mf * 16 + (lane >> 2) + h * 8;
            int qg = qt * 128 + row;
#pragma unroll
            for (int nf = 0; nf < 8; nf++) {
                int col = wn * 64 + nf * 8 + (lane & 3) * 2;
                int kg = kt * 128 + col;
                float2 v = make_float2(acc[mf][nf][h * 2] * SCALE,
                                       acc[mf][nf][h * 2 + 1] * SCALE);
                if (kg > qg) v.x = -1e30f;
                if (kg + 1 > qg) v.y = -1e30f;
                *(float2*)&Srow[(size_t)row * 2048 + col] = v;
            }
        }
}

__global__ void __launch_bounds__(256) softmax_kernel() {
    __shared__ float red[8];
    int r = blockIdx.x, q = r & 2047, tid = threadIdx.x;
    int L = ((q >> 7) + 1) << 7;
    float* row = g_S + (size_t)r * 2048;
    float m = -1e30f;
    for (int i = tid * 4; i < L; i += 1024) {
        float4 v = *(float4*)&row[i];
        m = fmaxf(m, fmaxf(fmaxf(v.x, v.y), fmaxf(v.z, v.w)));
    }
#pragma unroll
    for (int o = 16; o; o >>= 1) m = fmaxf(m, __shfl_xor_sync(~0u, m, o));
    if ((tid & 31) == 0) red[tid >> 5] = m;
    __syncthreads();
    m = fmaxf(fmaxf(fmaxf(red[0], red[1]), fmaxf(red[2], red[3])),
              fmaxf(fmaxf(red[4], red[5]), fmaxf(red[6], red[7])));
    float s = 0.f;
    for (int i = tid * 4; i < L; i += 1024) {
        float4 v = *(float4*)&row[i];
        v.x = __expf(v.x - m); v.y = __expf(v.y - m);
        v.z = __expf(v.z - m); v.w = __expf(v.w - m);
        s += v.x + v.y + v.z + v.w;
        *(float4*)&row[i] = v;
    }
#pragma unroll
    for (int o = 16; o; o >>= 1) s += __shfl_xor_sync(~0u, s, o);
    if ((tid & 31) == 0) red[tid >> 5] = s;
    __syncthreads();
    s = red[0] + red[1] + red[2] + red[3] + red[4] + red[5] + red[6] + red[7];
    float inv = 1.f / s;
    for (int i = tid * 4; i < L; i += 1024) {
        float4 v = *(float4*)&row[i];
        v.x *= inv; v.y *= inv; v.z *= inv; v.w *= inv;
        *(float4*)&row[i] = v;
    }
}

__global__ void __launch_bounds__(256, 1) pv_kernel(float* __restrict__ out) {
    extern __shared__ char smem[];
    int tid = threadIdx.x;
    int nt = blockIdx.x * 128, qt = blockIdx.y, b = blockIdx.z;
    ACC_DECL();
    run_gemm(smem, tid, g_S + ((size_t)b * 2048 + qt * 128) * 2048, 2048,
             g_VT + (size_t)b * 384 * 2048 + (size_t)nt * 2048, 2048, (qt + 1) * 4, acc);
    epi_rows(acc, out + ((size_t)b * 2048 + qt * 128) * 384 + nt, 384, tid);
}

extern "C" void kernel_launch(void* const* d_in, const int* in_sizes, int n_in,
                              void* d_out, int out_size) {
    const float* x  = (const float*)d_in[0];
    const float* Wq = (const float*)d_in[1];
    const float* Wk = (const float*)d_in[2];
    const float* Wv = (const float*)d_in[3];
    float* out = (float*)d_out;
    (void)in_sizes; (void)n_in; (void)out_size;

    cudaFuncSetAttribute(proj_kernel, cudaFuncAttributeMaxDynamicSharedMemorySize, SMEM_SZ);
    cudaFuncSetAttribute(qk_kernel,   cudaFuncAttributeMaxDynamicSharedMemorySize, SMEM_SZ);
    cudaFuncSetAttribute(pv_kernel,   cudaFuncAttributeMaxDynamicSharedMemorySize, SMEM_SZ);

    wt_kernel<<<dim3(3, 64), 256>>>(Wq, Wk, Wv);
    proj_kernel<<<dim3(3, 256, 3), 256, SMEM_SZ>>>(x);
    qk_kernel<<<dim3(136, 16), 256, SMEM_SZ>>>();
    softmax_kernel<<<32768, 256>>>();
    pv_kernel<<<dim3(3, 16, 16), 256, SMEM_SZ>>>(out);
}

// round 5
// speedup vs baseline: 4.1038x; 1.0944x over previous
#include <cuda_runtime.h>
#include <cuda_fp16.h>
#include <cstdint>

#define SCALE 0.05103103630798288f   // 384^-0.5
#define SMEM_QK 81920                 // 2 buf * 4 arrays * 10240
#define SMEM_PV 55296                 // 2 buf * (10240 + 2*8704)

__device__ __half g_Qh[16 * 2048 * 384], g_Ql[16 * 2048 * 384];
__device__ __half g_Kh[16 * 2048 * 384], g_Kl[16 * 2048 * 384];
__device__ __half g_Vh[16 * 2048 * 384], g_Vl[16 * 2048 * 384];
__device__ float  g_WT[3 * 384 * 384];
__device__ float  g_S[16ll * 2048 * 2048];
__device__ __half g_P[16ll * 2048 * 2048];

__device__ __forceinline__ uint32_t smem_u32(const void* p) {
    uint32_t a;
    asm("{ .reg .u64 t; cvta.to.shared.u64 t, %1; cvt.u32.u64 %0, t; }" : "=r"(a) : "l"(p));
    return a;
}
__device__ __forceinline__ void ldsm4(uint32_t addr, uint32_t* r) {
    asm volatile("ldmatrix.sync.aligned.m8n8.x4.shared.b16 {%0,%1,%2,%3}, [%4];"
        : "=r"(r[0]), "=r"(r[1]), "=r"(r[2]), "=r"(r[3]) : "r"(addr));
}
__device__ __forceinline__ void ldsm4t(uint32_t addr, uint32_t* r) {
    asm volatile("ldmatrix.sync.aligned.m8n8.x4.trans.shared.b16 {%0,%1,%2,%3}, [%4];"
        : "=r"(r[0]), "=r"(r[1]), "=r"(r[2]), "=r"(r[3]) : "r"(addr));
}
__device__ __forceinline__ void mmah(float* c, const uint32_t* a, const uint32_t* b) {
    asm volatile("mma.sync.aligned.m16n8k16.row.col.f32.f16.f16.f32 "
        "{%0,%1,%2,%3}, {%4,%5,%6,%7}, {%8,%9}, {%0,%1,%2,%3};"
        : "+f"(c[0]), "+f"(c[1]), "+f"(c[2]), "+f"(c[3])
        : "r"(a[0]), "r"(a[1]), "r"(a[2]), "r"(a[3]), "r"(b[0]), "r"(b[1]));
}

#define ACC_DECL()                                \
    float acc[2][8][4];                           \
    _Pragma("unroll") for (int i_ = 0; i_ < 2; i_++) \
    _Pragma("unroll") for (int j_ = 0; j_ < 8; j_++) \
    _Pragma("unroll") for (int q_ = 0; q_ < 4; q_++) acc[i_][j_][q_] = 0.f;

// ---- 3-pass split mainloop compute: AhBh + AhBl + AlBh ----
// arrays per buffer: Ah@0, Al@10240, Bh@20480, Bl@30720; 128 rows x 80B stride
__device__ __forceinline__ void compute_chunk3(uint32_t sbase, int wm, int wn, int lane,
                                               float acc[2][8][4]) {
    uint32_t aOff = (uint32_t)((wm * 32 + (lane & 15)) * 80 + (lane >> 4) * 16);
    uint32_t bOff = (uint32_t)((wn * 64 + ((lane >> 4) & 1) * 8 + (lane & 7)) * 80 +
                               ((lane >> 3) & 1) * 16);
#pragma unroll
    for (int ks = 0; ks < 2; ks++) {
        uint32_t ah[2][4], al[2][4], bh[8][2], bl[8][2];
#pragma unroll
        for (int mf = 0; mf < 2; mf++) {
            ldsm4(sbase + aOff + mf * 1280 + ks * 32, ah[mf]);
            ldsm4(sbase + 10240 + aOff + mf * 1280 + ks * 32, al[mf]);
        }
#pragma unroll
        for (int n2 = 0; n2 < 4; n2++) {
            uint32_t r[4];
            ldsm4(sbase + 20480 + bOff + n2 * 1280 + ks * 32, r);
            bh[n2 * 2][0] = r[0]; bh[n2 * 2][1] = r[1];
            bh[n2 * 2 + 1][0] = r[2]; bh[n2 * 2 + 1][1] = r[3];
            ldsm4(sbase + 30720 + bOff + n2 * 1280 + ks * 32, r);
            bl[n2 * 2][0] = r[0]; bl[n2 * 2][1] = r[1];
            bl[n2 * 2 + 1][0] = r[2]; bl[n2 * 2 + 1][1] = r[3];
        }
#pragma unroll
        for (int mf = 0; mf < 2; mf++)
#pragma unroll
            for (int nf = 0; nf < 8; nf++) {
                mmah(acc[mf][nf], ah[mf], bh[nf]);
                mmah(acc[mf][nf], ah[mf], bl[nf]);
                mmah(acc[mf][nf], al[mf], bh[nf]);
            }
    }
}

// ---- fp32 acc -> row-major fp32 store ----
__device__ __forceinline__ void epi_rows(float acc[2][8][4], float* __restrict__ Y,
                                         int stride, int tid) {
    int lane = tid & 31, wid = tid >> 5, wm = wid & 3, wn = wid >> 2;
#pragma unroll
    for (int mf = 0; mf < 2; mf++)
#pragma unroll
        for (int h = 0; h < 2; h++) {
            int row = wm * 32 + mf * 16 + (lane >> 2) + h * 8;
#pragma unroll
            for (int nf = 0; nf < 8; nf++) {
                float2 v = make_float2(acc[mf][nf][h * 2], acc[mf][nf][h * 2 + 1]);
                *(float2*)&Y[(size_t)row * stride + wn * 64 + nf * 8 + (lane & 3) * 2] = v;
            }
        }
}

__global__ void wt_kernel(const float* __restrict__ Wq, const float* __restrict__ Wk,
                          const float* __restrict__ Wv) {
    const float* W = (blockIdx.x == 0) ? Wq : ((blockIdx.x == 1) ? Wk : Wv);
    float* O = g_WT + (size_t)blockIdx.x * 384 * 384;
    int base = blockIdx.y * 2304;
    for (int i = base + threadIdx.x; i < base + 2304; i += 256) {
        int n = i / 384, k = i - n * 384;
        O[(size_t)n * 384 + k] = W[(size_t)k * 384 + n];
    }
}

// ---------------- proj: fp32 inputs, split-fp16 conversion in mainloop ----------------
struct __align__(8) hpair { __half2 a, b; };
__device__ __forceinline__ void split_store(char* hi, char* lo, float4 v, int off) {
    __half2 h0 = __floats2half2_rn(v.x, v.y);
    __half2 h1 = __floats2half2_rn(v.z, v.w);
    float2 f0 = __half22float2(h0), f1 = __half22float2(h1);
    hpair hp{h0, h1};
    hpair lp{__floats2half2_rn(v.x - f0.x, v.y - f0.y),
             __floats2half2_rn(v.z - f1.x, v.w - f1.y)};
    *(hpair*)(hi + off) = hp;
    *(hpair*)(lo + off) = lp;
}

__global__ void __launch_bounds__(256, 1) proj_kernel(const float* __restrict__ X) {
    extern __shared__ char smem[];
    int tid = threadIdx.x, lane = tid & 31, wid = tid >> 5, wm = wid & 3, wn = wid >> 2;
    uint32_t sb = smem_u32(smem);
    int nt = blockIdx.x * 128, mt = blockIdx.y * 128, z = blockIdx.z;
    const float* gA = X + (size_t)mt * 384;
    const float* gB = g_WT + (size_t)z * 384 * 384 + (size_t)nt * 384;
    ACC_DECL();

    float4 va[4], vb[4];
    auto ldg = [&](int c) {
#pragma unroll
        for (int i = 0; i < 4; i++) {
            int lin = tid + 256 * i, row = lin >> 3, c4 = (lin & 7) * 4;
            va[i] = *(const float4*)(gA + (size_t)row * 384 + c * 32 + c4);
            vb[i] = *(const float4*)(gB + (size_t)row * 384 + c * 32 + c4);
        }
    };
    auto stg = [&](char* buf) {
#pragma unroll
        for (int i = 0; i < 4; i++) {
            int lin = tid + 256 * i, row = lin >> 3, c4 = (lin & 7) * 4;
            int off = row * 80 + c4 * 2;
            split_store(buf,         buf + 10240, va[i], off);
            split_store(buf + 20480, buf + 30720, vb[i], off);
        }
    };
    ldg(0); stg(smem); __syncthreads();
    for (int c = 0; c < 12; c++) {
        if (c < 11) ldg(c + 1);
        compute_chunk3(sb + (uint32_t)(c & 1) * 40960u, wm, wn, lane, acc);
        if (c < 11) stg(smem + (size_t)((c + 1) & 1) * 40960);
        __syncthreads();
    }

    // epilogue: split-fp16 store (Q scaled)
    float s = (z == 0) ? SCALE : 1.f;
    __half* Yh = (z == 0) ? g_Qh : ((z == 1) ? g_Kh : g_Vh);
    __half* Yl = (z == 0) ? g_Ql : ((z == 1) ? g_Kl : g_Vl);
#pragma unroll
    for (int mf = 0; mf < 2; mf++)
#pragma unroll
        for (int h = 0; h < 2; h++) {
            int row = mt + wm * 32 + mf * 16 + (lane >> 2) + h * 8;
#pragma unroll
            for (int nf = 0; nf < 8; nf++) {
                int col = nt + wn * 64 + nf * 8 + (lane & 3) * 2;
                float vx = acc[mf][nf][h * 2] * s, vy = acc[mf][nf][h * 2 + 1] * s;
                __half2 hh = __floats2half2_rn(vx, vy);
                float2 ff = __half22float2(hh);
                __half2 ll = __floats2half2_rn(vx - ff.x, vy - ff.y);
                *(__half2*)&Yh[(size_t)row * 384 + col] = hh;
                *(__half2*)&Yl[(size_t)row * 384 + col] = ll;
            }
        }
}

// ---------------- qk: pure-copy mainloop from pre-split Q/K ----------------
__global__ void __launch_bounds__(256, 1) qk_kernel() {
    extern __shared__ char smem[];
    int tid = threadIdx.x, lane = tid & 31, wid = tid >> 5, wm = wid & 3, wn = wid >> 2;
    uint32_t sb = smem_u32(smem);
    int b = blockIdx.y, r_ = blockIdx.x, qt = 0;
    while (r_ > qt) { r_ -= qt + 1; qt++; }
    int kt = r_;
    size_t qb = ((size_t)b * 2048 + qt * 128) * 384;
    size_t kb = ((size_t)b * 2048 + kt * 128) * 384;
    ACC_DECL();

    uint4 rv[8];
    auto ldg = [&](int c) {
#pragma unroll
        for (int i = 0; i < 2; i++) {
            int lin = tid + 256 * i, rr = lin >> 2, cc = (lin & 3) * 8;
            size_t o = (size_t)rr * 384 + c * 32 + cc;
            rv[i * 4 + 0] = *(const uint4*)(g_Qh + qb + o);
            rv[i * 4 + 1] = *(const uint4*)(g_Ql + qb + o);
            rv[i * 4 + 2] = *(const uint4*)(g_Kh + kb + o);
            rv[i * 4 + 3] = *(const uint4*)(g_Kl + kb + o);
        }
    };
    auto stg = [&](char* buf) {
#pragma unroll
        for (int i = 0; i < 2; i++) {
            int lin = tid + 256 * i, rr = lin >> 2, cc = (lin & 3) * 8;
            int o = rr * 80 + cc * 2;
            *(uint4*)(buf + o)         = rv[i * 4 + 0];
            *(uint4*)(buf + 10240 + o) = rv[i * 4 + 1];
            *(uint4*)(buf + 20480 + o) = rv[i * 4 + 2];
            *(uint4*)(buf + 30720 + o) = rv[i * 4 + 3];
        }
    };
    ldg(0); stg(smem); __syncthreads();
    for (int c = 0; c < 12; c++) {
        if (c < 11) ldg(c + 1);
        compute_chunk3(sb + (uint32_t)(c & 1) * 40960u, wm, wn, lane, acc);
        if (c < 11) stg(smem + (size_t)((c + 1) & 1) * 40960);
        __syncthreads();
    }

    float* Srow = g_S + ((size_t)b * 2048 + qt * 128) * 2048 + (size_t)kt * 128;
#pragma unroll
    for (int mf = 0; mf < 2; mf++)
#pragma unroll
        for (int h = 0; h < 2; h++) {
            int row = wm * 32 + mf * 16 + (lane >> 2) + h * 8;
            int qg = qt * 128 + row;
#pragma unroll
            for (int nf = 0; nf < 8; nf++) {
                int col = wn * 64 + nf * 8 + (lane & 3) * 2;
                int kg = kt * 128 + col;
                float2 v = make_float2(acc[mf][nf][h * 2], acc[mf][nf][h * 2 + 1]);
                if (kg > qg) v.x = -1e30f;
                if (kg + 1 > qg) v.y = -1e30f;
                *(float2*)&Srow[(size_t)row * 2048 + col] = v;
            }
        }
}

// ---------------- softmax: S fp32 -> P fp16 ----------------
__global__ void __launch_bounds__(256) softmax_kernel() {
    __shared__ float red[8];
    int r = blockIdx.x, q = r & 2047, tid = threadIdx.x;
    int L = ((q >> 7) + 1) << 7;
    float* row = g_S + (size_t)r * 2048;
    __half* hp = g_P + (size_t)r * 2048;
    float m = -1e30f;
    for (int i = tid * 4; i < L; i += 1024) {
        float4 v = *(float4*)&row[i];
        m = fmaxf(m, fmaxf(fmaxf(v.x, v.y), fmaxf(v.z, v.w)));
    }
#pragma unroll
    for (int o = 16; o; o >>= 1) m = fmaxf(m, __shfl_xor_sync(~0u, m, o));
    if ((tid & 31) == 0) red[tid >> 5] = m;
    __syncthreads();
    m = fmaxf(fmaxf(fmaxf(red[0], red[1]), fmaxf(red[2], red[3])),
              fmaxf(fmaxf(red[4], red[5]), fmaxf(red[6], red[7])));
    float s = 0.f;
    for (int i = tid * 4; i < L; i += 1024) {
        float4 v = *(float4*)&row[i];
        v.x = __expf(v.x - m); v.y = __expf(v.y - m);
        v.z = __expf(v.z - m); v.w = __expf(v.w - m);
        s += v.x + v.y + v.z + v.w;
        *(float4*)&row[i] = v;
    }
#pragma unroll
    for (int o = 16; o; o >>= 1) s += __shfl_xor_sync(~0u, s, o);
    if ((tid & 31) == 0) red[tid >> 5] = s;
    __syncthreads();
    s = red[0] + red[1] + red[2] + red[3] + red[4] + red[5] + red[6] + red[7];
    float inv = 1.f / s;
    for (int i = tid * 4; i < L; i += 1024) {
        float4 v = *(float4*)&row[i];
        *(__half2*)&hp[i]     = __floats2half2_rn(v.x * inv, v.y * inv);
        *(__half2*)&hp[i + 2] = __floats2half2_rn(v.z * inv, v.w * inv);
    }
}

// ---------------- pv: 2-pass (P·Vh + P·Vl), V via ldmatrix.trans ----------------
// buffer: A(P)@0 (128x80B), Bh@10240 (32x272B), Bl@18944; stride 27648
__global__ void __launch_bounds__(256, 1) pv_kernel(float* __restrict__ out) {
    extern __shared__ char smem[];
    int tid = threadIdx.x, lane = tid & 31, wid = tid >> 5, wm = wid & 3, wn = wid >> 2;
    uint32_t sb = smem_u32(smem);
    int nt = blockIdx.x * 128, qt = 15 - (int)blockIdx.y, b = blockIdx.z;
    int nch = (qt + 1) * 4;
    const __half* Pb = g_P + ((size_t)b * 2048 + qt * 128) * 2048;
    const __half* Vh = g_Vh + (size_t)b * 2048 * 384 + nt;
    const __half* Vl = g_Vl + (size_t)b * 2048 * 384 + nt;
    ACC_DECL();

    uint4 rv[6];
    auto ldg = [&](int c) {
#pragma unroll
        for (int i = 0; i < 2; i++) {
            int lin = tid + 256 * i;
            int rr = lin >> 2, cc = (lin & 3) * 8;          // A: 128 x 32
            rv[i * 3 + 0] = *(const uint4*)(Pb + (size_t)rr * 2048 + c * 32 + cc);
            int r2 = lin >> 4, c2 = (lin & 15) * 8;         // B: 32 x 128
            size_t o = (size_t)(c * 32 + r2) * 384 + c2;
            rv[i * 3 + 1] = *(const uint4*)(Vh + o);
            rv[i * 3 + 2] = *(const uint4*)(Vl + o);
        }
    };
    auto stg = [&](char* buf) {
#pragma unroll
        for (int i = 0; i < 2; i++) {
            int lin = tid + 256 * i;
            int rr = lin >> 2, cc = (lin & 3) * 8;
            *(uint4*)(buf + rr * 80 + cc * 2) = rv[i * 3 + 0];
            int r2 = lin >> 4, c2 = (lin & 15) * 8;
            *(uint4*)(buf + 10240 + r2 * 272 + c2 * 2) = rv[i * 3 + 1];
            *(uint4*)(buf + 18944 + r2 * 272 + c2 * 2) = rv[i * 3 + 2];
        }
    };
    ldg(0); stg(smem); __syncthreads();

    uint32_t aOff = (uint32_t)((wm * 32 + (lane & 15)) * 80 + (lane >> 4) * 16);
    uint32_t bOff = (uint32_t)((((lane >> 3) & 1) * 8 + (lane & 7)) * 272 +
                               (wn * 64 + ((lane >> 4) & 1) * 8) * 2);
    for (int c = 0; c < nch; c++) {
        if (c + 1 < nch) ldg(c + 1);
        uint32_t sbase = sb + (uint32_t)(c & 1) * 27648u;
#pragma unroll
        for (int ks = 0; ks < 2; ks++) {
            uint32_t a[2][4], bh[8][2], bl[8][2];
#pragma unroll
            for (int mf = 0; mf < 2; mf++)
                ldsm4(sbase + aOff + mf * 1280 + ks * 32, a[mf]);
#pragma unroll
            for (int n2 = 0; n2 < 4; n2++) {
                uint32_t addr = sbase + 10240 + bOff + (uint32_t)(ks * 16 * 272 + n2 * 32);
                uint32_t r[4];
                ldsm4t(addr, r);
                bh[n2 * 2][0] = r[0]; bh[n2 * 2][1] = r[1];
                bh[n2 * 2 + 1][0] = r[2]; bh[n2 * 2 + 1][1] = r[3];
                ldsm4t(addr + 8704, r);
                bl[n2 * 2][0] = r[0]; bl[n2 * 2][1] = r[1];
                bl[n2 * 2 + 1][0] = r[2]; bl[n2 * 2 + 1][1] = r[3];
            }
#pragma unroll
            for (int mf = 0; mf < 2; mf++)
#pragma unroll
                for (int nf = 0; nf < 8; nf++) {
                    mmah(acc[mf][nf], a[mf], bh[nf]);
                    mmah(acc[mf][nf], a[mf], bl[nf]);
                }
        }
        if (c + 1 < nch) stg(smem + (size_t)((c + 1) & 1) * 27648);
        __syncthreads();
    }
    epi_rows(acc, out + ((size_t)b * 2048 + qt * 128) * 384 + nt, 384, tid);
}

extern "C" void kernel_launch(void* const* d_in, const int* in_sizes, int n_in,
                              void* d_out, int out_size) {
    const float* x  = (const float*)d_in[0];
    const float* Wq = (const float*)d_in[1];
    const float* Wk = (const float*)d_in[2];
    const float* Wv = (const float*)d_in[3];
    float* out = (float*)d_out;
    (void)in_sizes; (void)n_in; (void)out_size;

    cudaFuncSetAttribute(proj_kernel, cudaFuncAttributeMaxDynamicSharedMemorySize, SMEM_QK);
    cudaFuncSetAttribute(qk_kernel,   cudaFuncAttributeMaxDynamicSharedMemorySize, SMEM_QK);
    cudaFuncSetAttribute(pv_kernel,   cudaFuncAttributeMaxDynamicSharedMemorySize, SMEM_PV);

    wt_kernel<<<dim3(3, 64), 256>>>(Wq, Wk, Wv);
    proj_kernel<<<dim3(3, 256, 3), 256, SMEM_QK>>>(x);
    qk_kernel<<<dim3(136, 16), 256, SMEM_QK>>>();
    softmax_kernel<<<32768, 256>>>();
    pv_kernel<<<dim3(3, 16, 16), 256, SMEM_PV>>>(out);
}

// round 6
// speedup vs baseline: 6.6220x; 1.6136x over previous
#include <cuda_runtime.h>
#include <cuda_fp16.h>
#include <cstdint>

#define SCALE 0.05103103630798288f   // 384^-0.5
#define SMEM_PROJ 61440               // 2 buf * (A 10240 + Bh 10240 + Bl 10240)
#define SMEM_QK   40960               // 2 buf * (A 10240 + B 10240)
#define SMEM_PV   37888               // 2 buf * (A 10240 + B 8704)

__device__ __half g_Qh[16 * 2048 * 384];
__device__ __half g_Kh[16 * 2048 * 384];
__device__ __half g_Vh[16 * 2048 * 384];
__device__ __half g_WhT[3 * 384 * 384], g_WlT[3 * 384 * 384];
__device__ float  g_S[16ll * 2048 * 2048];
__device__ __half g_P[16ll * 2048 * 2048];

__device__ __forceinline__ uint32_t smem_u32(const void* p) {
    uint32_t a;
    asm("{ .reg .u64 t; cvta.to.shared.u64 t, %1; cvt.u32.u64 %0, t; }" : "=r"(a) : "l"(p));
    return a;
}
__device__ __forceinline__ void ldsm4(uint32_t addr, uint32_t* r) {
    asm volatile("ldmatrix.sync.aligned.m8n8.x4.shared.b16 {%0,%1,%2,%3}, [%4];"
        : "=r"(r[0]), "=r"(r[1]), "=r"(r[2]), "=r"(r[3]) : "r"(addr));
}
__device__ __forceinline__ void ldsm4t(uint32_t addr, uint32_t* r) {
    asm volatile("ldmatrix.sync.aligned.m8n8.x4.trans.shared.b16 {%0,%1,%2,%3}, [%4];"
        : "=r"(r[0]), "=r"(r[1]), "=r"(r[2]), "=r"(r[3]) : "r"(addr));
}
__device__ __forceinline__ void mmah(float* c, const uint32_t* a, const uint32_t* b) {
    asm volatile("mma.sync.aligned.m16n8k16.row.col.f32.f16.f16.f32 "
        "{%0,%1,%2,%3}, {%4,%5,%6,%7}, {%8,%9}, {%0,%1,%2,%3};"
        : "+f"(c[0]), "+f"(c[1]), "+f"(c[2]), "+f"(c[3])
        : "r"(a[0]), "r"(a[1]), "r"(a[2]), "r"(a[3]), "r"(b[0]), "r"(b[1]));
}

#define ACC_DECL()                                   \
    float acc[2][8][4];                              \
    _Pragma("unroll") for (int i_ = 0; i_ < 2; i_++) \
    _Pragma("unroll") for (int j_ = 0; j_ < 8; j_++) \
    _Pragma("unroll") for (int q_ = 0; q_ < 4; q_++) acc[i_][j_][q_] = 0.f;

#define AOFF(wm, lane) ((uint32_t)(((wm) * 32 + ((lane) & 15)) * 80 + ((lane) >> 4) * 16))
#define BOFF(wn, lane) ((uint32_t)(((wn) * 64 + (((lane) >> 4) & 1) * 8 + ((lane) & 7)) * 80 + \
                                   (((lane) >> 3) & 1) * 16))

// 1-pass chunk: A@0, B@10240
__device__ __forceinline__ void chunk1(uint32_t sbase, uint32_t aOff, uint32_t bOff,
                                       float acc[2][8][4]) {
#pragma unroll
    for (int ks = 0; ks < 2; ks++) {
        uint32_t a[2][4], b[8][2];
#pragma unroll
        for (int mf = 0; mf < 2; mf++) ldsm4(sbase + aOff + mf * 1280 + ks * 32, a[mf]);
#pragma unroll
        for (int n2 = 0; n2 < 4; n2++) {
            uint32_t r[4];
            ldsm4(sbase + 10240 + bOff + n2 * 1280 + ks * 32, r);
            b[n2 * 2][0] = r[0]; b[n2 * 2][1] = r[1];
            b[n2 * 2 + 1][0] = r[2]; b[n2 * 2 + 1][1] = r[3];
        }
#pragma unroll
        for (int mf = 0; mf < 2; mf++)
#pragma unroll
            for (int nf = 0; nf < 8; nf++) mmah(acc[mf][nf], a[mf], b[nf]);
    }
}

// 2-pass chunk: A@0, Bh@10240, Bl@20480  (A·Bh + A·Bl)
__device__ __forceinline__ void chunk2(uint32_t sbase, uint32_t aOff, uint32_t bOff,
                                       float acc[2][8][4]) {
#pragma unroll
    for (int ks = 0; ks < 2; ks++) {
        uint32_t a[2][4], bh[8][2], bl[8][2];
#pragma unroll
        for (int mf = 0; mf < 2; mf++) ldsm4(sbase + aOff + mf * 1280 + ks * 32, a[mf]);
#pragma unroll
        for (int n2 = 0; n2 < 4; n2++) {
            uint32_t r[4];
            ldsm4(sbase + 10240 + bOff + n2 * 1280 + ks * 32, r);
            bh[n2 * 2][0] = r[0]; bh[n2 * 2][1] = r[1];
            bh[n2 * 2 + 1][0] = r[2]; bh[n2 * 2 + 1][1] = r[3];
            ldsm4(sbase + 20480 + bOff + n2 * 1280 + ks * 32, r);
            bl[n2 * 2][0] = r[0]; bl[n2 * 2][1] = r[1];
            bl[n2 * 2 + 1][0] = r[2]; bl[n2 * 2 + 1][1] = r[3];
        }
#pragma unroll
        for (int mf = 0; mf < 2; mf++)
#pragma unroll
            for (int nf = 0; nf < 8; nf++) {
                mmah(acc[mf][nf], a[mf], bh[nf]);
                mmah(acc[mf][nf], a[mf], bl[nf]);
            }
    }
}

struct __align__(8) hpair { __half2 a, b; };
__device__ __forceinline__ hpair to_h(float4 v) {
    hpair r; r.a = __floats2half2_rn(v.x, v.y); r.b = __floats2half2_rn(v.z, v.w); return r;
}

// ---------------- wt: W -> split-fp16 W^T ----------------
__global__ void wt_kernel(const float* __restrict__ Wq, const float* __restrict__ Wk,
                          const float* __restrict__ Wv) {
    const float* W = (blockIdx.x == 0) ? Wq : ((blockIdx.x == 1) ? Wk : Wv);
    __half* Oh = g_WhT + (size_t)blockIdx.x * 147456;
    __half* Ol = g_WlT + (size_t)blockIdx.x * 147456;
    int base = blockIdx.y * 2304;
    for (int i = base + threadIdx.x; i < base + 2304; i += 256) {
        int n = i / 384, k = i - n * 384;
        float v = W[(size_t)k * 384 + n];
        __half h = __float2half_rn(v);
        Oh[(size_t)n * 384 + k] = h;
        Ol[(size_t)n * 384 + k] = __float2half_rn(v - __half2float(h));
    }
}

// ---------------- proj: 2-pass (X single fp16, W pre-split) ----------------
__global__ void __launch_bounds__(256, 1) proj_kernel(const float* __restrict__ X) {
    extern __shared__ char smem[];
    int tid = threadIdx.x, lane = tid & 31, wid = tid >> 5, wm = wid & 3, wn = wid >> 2;
    uint32_t sb = smem_u32(smem);
    int nt = blockIdx.x * 128, mt = blockIdx.y * 128, z = blockIdx.z;
    const float*  gA  = X + (size_t)mt * 384;
    const __half* gBh = g_WhT + (size_t)z * 147456 + (size_t)nt * 384;
    const __half* gBl = g_WlT + (size_t)z * 147456 + (size_t)nt * 384;
    ACC_DECL();

    float4 va[4]; uint4 vb[4];
    auto ldg = [&](int c) {
#pragma unroll
        for (int i = 0; i < 4; i++) {
            int lin = tid + 256 * i, row = lin >> 3, c4 = (lin & 7) * 4;
            va[i] = *(const float4*)(gA + (size_t)row * 384 + c * 32 + c4);
        }
#pragma unroll
        for (int i = 0; i < 2; i++) {
            int lin = tid + 256 * i, rr = lin >> 2, cc = (lin & 3) * 8;
            size_t o = (size_t)rr * 384 + c * 32 + cc;
            vb[i * 2 + 0] = *(const uint4*)(gBh + o);
            vb[i * 2 + 1] = *(const uint4*)(gBl + o);
        }
    };
    auto stg = [&](char* buf) {
#pragma unroll
        for (int i = 0; i < 4; i++) {
            int lin = tid + 256 * i, row = lin >> 3, c4 = (lin & 7) * 4;
            *(hpair*)(buf + row * 80 + c4 * 2) = to_h(va[i]);
        }
#pragma unroll
        for (int i = 0; i < 2; i++) {
            int lin = tid + 256 * i, rr = lin >> 2, cc = (lin & 3) * 8;
            int o = rr * 80 + cc * 2;
            *(uint4*)(buf + 10240 + o) = vb[i * 2 + 0];
            *(uint4*)(buf + 20480 + o) = vb[i * 2 + 1];
        }
    };
    uint32_t aOff = AOFF(wm, lane), bOff = BOFF(wn, lane);
    ldg(0); stg(smem); __syncthreads();
    for (int c = 0; c < 12; c++) {
        if (c < 11) ldg(c + 1);
        chunk2(sb + (uint32_t)(c & 1) * 30720u, aOff, bOff, acc);
        if (c < 11) stg(smem + (size_t)((c + 1) & 1) * 30720);
        __syncthreads();
    }

    float s = (z == 0) ? SCALE : 1.f;
    __half* Yh = (z == 0) ? g_Qh : ((z == 1) ? g_Kh : g_Vh);
#pragma unroll
    for (int mf = 0; mf < 2; mf++)
#pragma unroll
        for (int h = 0; h < 2; h++) {
            int row = mt + wm * 32 + mf * 16 + (lane >> 2) + h * 8;
#pragma unroll
            for (int nf = 0; nf < 8; nf++) {
                int col = nt + wn * 64 + nf * 8 + (lane & 3) * 2;
                *(__half2*)&Yh[(size_t)row * 384 + col] =
                    __floats2half2_rn(acc[mf][nf][h * 2] * s, acc[mf][nf][h * 2 + 1] * s);
            }
        }
}

// ---------------- qk: 1-pass pure-copy mainloop ----------------
__global__ void __launch_bounds__(256, 2) qk_kernel() {
    extern __shared__ char smem[];
    int tid = threadIdx.x, lane = tid & 31, wid = tid >> 5, wm = wid & 3, wn = wid >> 2;
    uint32_t sb = smem_u32(smem);
    int b = blockIdx.y, r_ = blockIdx.x, qt = 0;
    while (r_ > qt) { r_ -= qt + 1; qt++; }
    int kt = r_;
    size_t qb = ((size_t)b * 2048 + qt * 128) * 384;
    size_t kb = ((size_t)b * 2048 + kt * 128) * 384;
    ACC_DECL();

    uint4 rv[4];
    auto ldg = [&](int c) {
#pragma unroll
        for (int i = 0; i < 2; i++) {
            int lin = tid + 256 * i, rr = lin >> 2, cc = (lin & 3) * 8;
            size_t o = (size_t)rr * 384 + c * 32 + cc;
            rv[i * 2 + 0] = *(const uint4*)(g_Qh + qb + o);
            rv[i * 2 + 1] = *(const uint4*)(g_Kh + kb + o);
        }
    };
    auto stg = [&](char* buf) {
#pragma unroll
        for (int i = 0; i < 2; i++) {
            int lin = tid + 256 * i, rr = lin >> 2, cc = (lin & 3) * 8;
            int o = rr * 80 + cc * 2;
            *(uint4*)(buf + o)         = rv[i * 2 + 0];
            *(uint4*)(buf + 10240 + o) = rv[i * 2 + 1];
        }
    };
    uint32_t aOff = AOFF(wm, lane), bOff = BOFF(wn, lane);
    ldg(0); stg(smem); __syncthreads();
    for (int c = 0; c < 12; c++) {
        if (c < 11) ldg(c + 1);
        chunk1(sb + (uint32_t)(c & 1) * 20480u, aOff, bOff, acc);
        if (c < 11) stg(smem + (size_t)((c + 1) & 1) * 20480);
        __syncthreads();
    }

    float* Srow = g_S + ((size_t)b * 2048 + qt * 128) * 2048 + (size_t)kt * 128;
#pragma unroll
    for (int mf = 0; mf < 2; mf++)
#pragma unroll
        for (int h = 0; h < 2; h++) {
            int row = wm * 32 + mf * 16 + (lane >> 2) + h * 8;
            int qg = qt * 128 + row;
#pragma unroll
            for (int nf = 0; nf < 8; nf++) {
                int col = wn * 64 + nf * 8 + (lane & 3) * 2;
                int kg = kt * 128 + col;
                float2 v = make_float2(acc[mf][nf][h * 2], acc[mf][nf][h * 2 + 1]);
                if (kg > qg) v.x = -1e30f;
                if (kg + 1 > qg) v.y = -1e30f;
                *(float2*)&Srow[(size_t)row * 2048 + col] = v;
            }
        }
}

// ---------------- softmax: register-resident, single S read, P fp16 write ----------------
__global__ void __launch_bounds__(256) softmax_kernel() {
    __shared__ float red[8];
    int r = blockIdx.x, q = r & 2047, tid = threadIdx.x;
    int L = ((q >> 7) + 1) << 7;
    const float* row = g_S + (size_t)r * 2048;
    __half* hp = g_P + (size_t)r * 2048;
    int i0 = tid * 4, i1 = i0 + 1024;
    bool h0 = i0 < L, h1 = i1 < L;
    float4 v0 = h0 ? *(const float4*)&row[i0] : make_float4(-1e30f, -1e30f, -1e30f, -1e30f);
    float4 v1 = h1 ? *(const float4*)&row[i1] : make_float4(-1e30f, -1e30f, -1e30f, -1e30f);

    float m = fmaxf(fmaxf(fmaxf(v0.x, v0.y), fmaxf(v0.z, v0.w)),
                    fmaxf(fmaxf(v1.x, v1.y), fmaxf(v1.z, v1.w)));
#pragma unroll
    for (int o = 16; o; o >>= 1) m = fmaxf(m, __shfl_xor_sync(~0u, m, o));
    if ((tid & 31) == 0) red[tid >> 5] = m;
    __syncthreads();
    m = fmaxf(fmaxf(fmaxf(red[0], red[1]), fmaxf(red[2], red[3])),
              fmaxf(fmaxf(red[4], red[5]), fmaxf(red[6], red[7])));

    v0.x = __expf(v0.x - m); v0.y = __expf(v0.y - m);
    v0.z = __expf(v0.z - m); v0.w = __expf(v0.w - m);
    v1.x = __expf(v1.x - m); v1.y = __expf(v1.y - m);
    v1.z = __expf(v1.z - m); v1.w = __expf(v1.w - m);
    float s = v0.x + v0.y + v0.z + v0.w + v1.x + v1.y + v1.z + v1.w;
#pragma unroll
    for (int o = 16; o; o >>= 1) s += __shfl_xor_sync(~0u, s, o);
    __syncthreads();
    if ((tid & 31) == 0) red[tid >> 5] = s;
    __syncthreads();
    s = red[0] + red[1] + red[2] + red[3] + red[4] + red[5] + red[6] + red[7];
    float inv = 1.f / s;

    if (h0) {
        *(__half2*)&hp[i0]     = __floats2half2_rn(v0.x * inv, v0.y * inv);
        *(__half2*)&hp[i0 + 2] = __floats2half2_rn(v0.z * inv, v0.w * inv);
    }
    if (h1) {
        *(__half2*)&hp[i1]     = __floats2half2_rn(v1.x * inv, v1.y * inv);
        *(__half2*)&hp[i1 + 2] = __floats2half2_rn(v1.z * inv, v1.w * inv);
    }
}

// ---------------- pv: 1-pass (P fp16 · V fp16 via ldmatrix.trans) ----------------
__global__ void __launch_bounds__(256, 2) pv_kernel(float* __restrict__ out) {
    extern __shared__ char smem[];
    int tid = threadIdx.x, lane = tid & 31, wid = tid >> 5, wm = wid & 3, wn = wid >> 2;
    uint32_t sb = smem_u32(smem);
    int nt = blockIdx.x * 128, qt = 15 - (int)blockIdx.y, b = blockIdx.z;
    int nch = (qt + 1) * 4;
    const __half* Pb = g_P + ((size_t)b * 2048 + qt * 128) * 2048;
    const __half* Vh = g_Vh + (size_t)b * 2048 * 384 + nt;
    ACC_DECL();

    uint4 rv[4];
    auto ldg = [&](int c) {
#pragma unroll
        for (int i = 0; i < 2; i++) {
            int lin = tid + 256 * i;
            int rr = lin >> 2, cc = (lin & 3) * 8;            // A: 128 x 32
            rv[i * 2 + 0] = *(const uint4*)(Pb + (size_t)rr * 2048 + c * 32 + cc);
            int r2 = lin >> 4, c2 = (lin & 15) * 8;           // B: 32 x 128
            rv[i * 2 + 1] = *(const uint4*)(Vh + (size_t)(c * 32 + r2) * 384 + c2);
        }
    };
    auto stg = [&](char* buf) {
#pragma unroll
        for (int i = 0; i < 2; i++) {
            int lin = tid + 256 * i;
            int rr = lin >> 2, cc = (lin & 3) * 8;
            *(uint4*)(buf + rr * 80 + cc * 2) = rv[i * 2 + 0];
            int r2 = lin >> 4, c2 = (lin & 15) * 8;
            *(uint4*)(buf + 10240 + r2 * 272 + c2 * 2) = rv[i * 2 + 1];
        }
    };
    ldg(0); stg(smem); __syncthreads();

    uint32_t aOff = AOFF(wm, lane);
    uint32_t bOff = (uint32_t)((((lane >> 3) & 1) * 8 + (lane & 7)) * 272 +
                               (wn * 64 + ((lane >> 4) & 1) * 8) * 2);
    for (int c = 0; c < nch; c++) {
        if (c + 1 < nch) ldg(c + 1);
        uint32_t sbase = sb + (uint32_t)(c & 1) * 18944u;
#pragma unroll
        for (int ks = 0; ks < 2; ks++) {
            uint32_t a[2][4], bh[8][2];
#pragma unroll
            for (int mf = 0; mf < 2; mf++) ldsm4(sbase + aOff + mf * 1280 + ks * 32, a[mf]);
#pragma unroll
            for (int n2 = 0; n2 < 4; n2++) {
                uint32_t r[4];
                ldsm4t(sbase + 10240 + bOff + (uint32_t)(ks * 16 * 272 + n2 * 32), r);
                bh[n2 * 2][0] = r[0]; bh[n2 * 2][1] = r[1];
                bh[n2 * 2 + 1][0] = r[2]; bh[n2 * 2 + 1][1] = r[3];
            }
#pragma unroll
            for (int mf = 0; mf < 2; mf++)
#pragma unroll
                for (int nf = 0; nf < 8; nf++) mmah(acc[mf][nf], a[mf], bh[nf]);
        }
        if (c + 1 < nch) stg(smem + (size_t)((c + 1) & 1) * 18944);
        __syncthreads();
    }

    float* Y = out + ((size_t)b * 2048 + qt * 128) * 384 + nt;
#pragma unroll
    for (int mf = 0; mf < 2; mf++)
#pragma unroll
        for (int h = 0; h < 2; h++) {
            int row = wm * 32 + mf * 16 + (lane >> 2) + h * 8;
#pragma unroll
            for (int nf = 0; nf < 8; nf++) {
                float2 v = make_float2(acc[mf][nf][h * 2], acc[mf][nf][h * 2 + 1]);
                *(float2*)&Y[(size_t)row * 384 + wn * 64 + nf * 8 + (lane & 3) * 2] = v;
            }
        }
}

extern "C" void kernel_launch(void* const* d_in, const int* in_sizes, int n_in,
                              void* d_out, int out_size) {
    const float* x  = (const float*)d_in[0];
    const float* Wq = (const float*)d_in[1];
    const float* Wk = (const float*)d_in[2];
    const float* Wv = (const float*)d_in[3];
    float* out = (float*)d_out;
    (void)in_sizes; (void)n_in; (void)out_size;

    cudaFuncSetAttribute(proj_kernel, cudaFuncAttributeMaxDynamicSharedMemorySize, SMEM_PROJ);
    cudaFuncSetAttribute(qk_kernel,   cudaFuncAttributeMaxDynamicSharedMemorySize, SMEM_QK);
    cudaFuncSetAttribute(pv_kernel,   cudaFuncAttributeMaxDynamicSharedMemorySize, SMEM_PV);

    wt_kernel<<<dim3(3, 64), 256>>>(Wq, Wk, Wv);
    proj_kernel<<<dim3(3, 256, 3), 256, SMEM_PROJ>>>(x);
    qk_kernel<<<dim3(136, 16), 256, SMEM_QK>>>();
    softmax_kernel<<<32768, 256>>>();
    pv_kernel<<<dim3(3, 16, 16), 256, SMEM_PV>>>(out);
}

// round 7
// speedup vs baseline: 8.2181x; 1.2410x over previous
#include <cuda_runtime.h>
#include <cuda_fp16.h>
#include <cstdint>

#define SCALE 0.05103103630798288f   // 384^-0.5
#define SMEM_GEMM 40960               // 2 buf * (A 10240 + B 10240)
#define SMEM_PV   37888               // 2 buf * (A 10240 + B 8704)

__device__ __half g_Qh[16 * 2048 * 384];
__device__ __half g_Kh[16 * 2048 * 384];
__device__ __half g_Vh[16 * 2048 * 384];
__device__ __half g_WhT[3 * 384 * 384];
__device__ float  g_S[16ll * 2048 * 2048];
__device__ __half g_P[16ll * 2048 * 2048];

__device__ __forceinline__ uint32_t smem_u32(const void* p) {
    uint32_t a;
    asm("{ .reg .u64 t; cvta.to.shared.u64 t, %1; cvt.u32.u64 %0, t; }" : "=r"(a) : "l"(p));
    return a;
}
__device__ __forceinline__ void ldsm4(uint32_t addr, uint32_t* r) {
    asm volatile("ldmatrix.sync.aligned.m8n8.x4.shared.b16 {%0,%1,%2,%3}, [%4];"
        : "=r"(r[0]), "=r"(r[1]), "=r"(r[2]), "=r"(r[3]) : "r"(addr));
}
__device__ __forceinline__ void ldsm4t(uint32_t addr, uint32_t* r) {
    asm volatile("ldmatrix.sync.aligned.m8n8.x4.trans.shared.b16 {%0,%1,%2,%3}, [%4];"
        : "=r"(r[0]), "=r"(r[1]), "=r"(r[2]), "=r"(r[3]) : "r"(addr));
}
__device__ __forceinline__ void mmah(float* c, const uint32_t* a, const uint32_t* b) {
    asm volatile("mma.sync.aligned.m16n8k16.row.col.f32.f16.f16.f32 "
        "{%0,%1,%2,%3}, {%4,%5,%6,%7}, {%8,%9}, {%0,%1,%2,%3};"
        : "+f"(c[0]), "+f"(c[1]), "+f"(c[2]), "+f"(c[3])
        : "r"(a[0]), "r"(a[1]), "r"(a[2]), "r"(a[3]), "r"(b[0]), "r"(b[1]));
}

#define ACC_DECL()                                   \
    float acc[2][8][4];                              \
    _Pragma("unroll") for (int i_ = 0; i_ < 2; i_++) \
    _Pragma("unroll") for (int j_ = 0; j_ < 8; j_++) \
    _Pragma("unroll") for (int q_ = 0; q_ < 4; q_++) acc[i_][j_][q_] = 0.f;

#define AOFF(wm, lane) ((uint32_t)(((wm) * 32 + ((lane) & 15)) * 80 + ((lane) >> 4) * 16))
#define BOFF(wn, lane) ((uint32_t)(((wn) * 64 + (((lane) >> 4) & 1) * 8 + ((lane) & 7)) * 80 + \
                                   (((lane) >> 3) & 1) * 16))

// 1-pass K=32 chunk: A@0, B@10240; 128 rows x 80B stride
__device__ __forceinline__ void chunk1(uint32_t sbase, uint32_t aOff, uint32_t bOff,
                                       float acc[2][8][4]) {
#pragma unroll
    for (int ks = 0; ks < 2; ks++) {
        uint32_t a[2][4], b[8][2];
#pragma unroll
        for (int mf = 0; mf < 2; mf++) ldsm4(sbase + aOff + mf * 1280 + ks * 32, a[mf]);
#pragma unroll
        for (int n2 = 0; n2 < 4; n2++) {
            uint32_t r[4];
            ldsm4(sbase + 10240 + bOff + n2 * 1280 + ks * 32, r);
            b[n2 * 2][0] = r[0]; b[n2 * 2][1] = r[1];
            b[n2 * 2 + 1][0] = r[2]; b[n2 * 2 + 1][1] = r[3];
        }
#pragma unroll
        for (int mf = 0; mf < 2; mf++)
#pragma unroll
            for (int nf = 0; nf < 8; nf++) mmah(acc[mf][nf], a[mf], b[nf]);
    }
}

struct __align__(8) hpair { __half2 a, b; };
__device__ __forceinline__ hpair to_h(float4 v) {
    hpair r; r.a = __floats2half2_rn(v.x, v.y); r.b = __floats2half2_rn(v.z, v.w); return r;
}

// ---------------- wt: W -> fp16 W^T ----------------
__global__ void wt_kernel(const float* __restrict__ Wq, const float* __restrict__ Wk,
                          const float* __restrict__ Wv) {
    const float* W = (blockIdx.x == 0) ? Wq : ((blockIdx.x == 1) ? Wk : Wv);
    __half* Oh = g_WhT + (size_t)blockIdx.x * 147456;
    int base = blockIdx.y * 2304;
    for (int i = base + threadIdx.x; i < base + 2304; i += 256) {
        int n = i / 384, k = i - n * 384;
        Oh[(size_t)n * 384 + k] = __float2half_rn(W[(size_t)k * 384 + n]);
    }
}

// ---------------- proj: 1-pass (X->fp16 on the fly, W fp16 pre-transposed) ----------------
__global__ void __launch_bounds__(256, 2) proj_kernel(const float* __restrict__ X) {
    extern __shared__ char smem[];
    int tid = threadIdx.x, lane = tid & 31, wid = tid >> 5, wm = wid & 3, wn = wid >> 2;
    uint32_t sb = smem_u32(smem);
    int nt = blockIdx.x * 128, mt = blockIdx.y * 128, z = blockIdx.z;
    const float*  gA = X + (size_t)mt * 384;
    const __half* gB = g_WhT + (size_t)z * 147456 + (size_t)nt * 384;
    ACC_DECL();

    float4 va[4]; uint4 vb[2];
    auto ldg = [&](int c) {
#pragma unroll
        for (int i = 0; i < 4; i++) {
            int lin = tid + 256 * i, row = lin >> 3, c4 = (lin & 7) * 4;
            va[i] = *(const float4*)(gA + (size_t)row * 384 + c * 32 + c4);
        }
#pragma unroll
        for (int i = 0; i < 2; i++) {
            int lin = tid + 256 * i, rr = lin >> 2, cc = (lin & 3) * 8;
            vb[i] = *(const uint4*)(gB + (size_t)rr * 384 + c * 32 + cc);
        }
    };
    auto stg = [&](char* buf) {
#pragma unroll
        for (int i = 0; i < 4; i++) {
            int lin = tid + 256 * i, row = lin >> 3, c4 = (lin & 7) * 4;
            *(hpair*)(buf + row * 80 + c4 * 2) = to_h(va[i]);
        }
#pragma unroll
        for (int i = 0; i < 2; i++) {
            int lin = tid + 256 * i, rr = lin >> 2, cc = (lin & 3) * 8;
            *(uint4*)(buf + 10240 + rr * 80 + cc * 2) = vb[i];
        }
    };
    uint32_t aOff = AOFF(wm, lane), bOff = BOFF(wn, lane);
    ldg(0); stg(smem); __syncthreads();
    for (int c = 0; c < 12; c++) {
        if (c < 11) ldg(c + 1);
        chunk1(sb + (uint32_t)(c & 1) * 20480u, aOff, bOff, acc);
        if (c < 11) stg(smem + (size_t)((c + 1) & 1) * 20480);
        __syncthreads();
    }

    float s = (z == 0) ? SCALE : 1.f;
    __half* Yh = (z == 0) ? g_Qh : ((z == 1) ? g_Kh : g_Vh);
#pragma unroll
    for (int mf = 0; mf < 2; mf++)
#pragma unroll
        for (int h = 0; h < 2; h++) {
            int row = mt + wm * 32 + mf * 16 + (lane >> 2) + h * 8;
#pragma unroll
            for (int nf = 0; nf < 8; nf++) {
                int col = nt + wn * 64 + nf * 8 + (lane & 3) * 2;
                *(__half2*)&Yh[(size_t)row * 384 + col] =
                    __floats2half2_rn(acc[mf][nf][h * 2] * s, acc[mf][nf][h * 2 + 1] * s);
            }
        }
}

// ---------------- qk: 1-pass pure-copy mainloop ----------------
__global__ void __launch_bounds__(256, 2) qk_kernel() {
    extern __shared__ char smem[];
    int tid = threadIdx.x, lane = tid & 31, wid = tid >> 5, wm = wid & 3, wn = wid >> 2;
    uint32_t sb = smem_u32(smem);
    int b = blockIdx.y, r_ = blockIdx.x, qt = 0;
    while (r_ > qt) { r_ -= qt + 1; qt++; }
    int kt = r_;
    size_t qb = ((size_t)b * 2048 + qt * 128) * 384;
    size_t kb = ((size_t)b * 2048 + kt * 128) * 384;
    ACC_DECL();

    uint4 rv[4];
    auto ldg = [&](int c) {
#pragma unroll
        for (int i = 0; i < 2; i++) {
            int lin = tid + 256 * i, rr = lin >> 2, cc = (lin & 3) * 8;
            size_t o = (size_t)rr * 384 + c * 32 + cc;
            rv[i * 2 + 0] = *(const uint4*)(g_Qh + qb + o);
            rv[i * 2 + 1] = *(const uint4*)(g_Kh + kb + o);
        }
    };
    auto stg = [&](char* buf) {
#pragma unroll
        for (int i = 0; i < 2; i++) {
            int lin = tid + 256 * i, rr = lin >> 2, cc = (lin & 3) * 8;
            int o = rr * 80 + cc * 2;
            *(uint4*)(buf + o)         = rv[i * 2 + 0];
            *(uint4*)(buf + 10240 + o) = rv[i * 2 + 1];
        }
    };
    uint32_t aOff = AOFF(wm, lane), bOff = BOFF(wn, lane);
    ldg(0); stg(smem); __syncthreads();
    for (int c = 0; c < 12; c++) {
        if (c < 11) ldg(c + 1);
        chunk1(sb + (uint32_t)(c & 1) * 20480u, aOff, bOff, acc);
        if (c < 11) stg(smem + (size_t)((c + 1) & 1) * 20480);
        __syncthreads();
    }

    float* Srow = g_S + ((size_t)b * 2048 + qt * 128) * 2048 + (size_t)kt * 128;
#pragma unroll
    for (int mf = 0; mf < 2; mf++)
#pragma unroll
        for (int h = 0; h < 2; h++) {
            int row = wm * 32 + mf * 16 + (lane >> 2) + h * 8;
            int qg = qt * 128 + row;
#pragma unroll
            for (int nf = 0; nf < 8; nf++) {
                int col = wn * 64 + nf * 8 + (lane & 3) * 2;
                int kg = kt * 128 + col;
                float2 v = make_float2(acc[mf][nf][h * 2], acc[mf][nf][h * 2 + 1]);
                if (kg > qg) v.x = -1e30f;
                if (kg + 1 > qg) v.y = -1e30f;
                *(float2*)&Srow[(size_t)row * 2048 + col] = v;
            }
        }
}

// ---------------- softmax: register-resident, S fp32 read once, P fp16 write ----------------
__global__ void __launch_bounds__(256) softmax_kernel() {
    __shared__ float red[8];
    int r = blockIdx.x, q = r & 2047, tid = threadIdx.x;
    int L = ((q >> 7) + 1) << 7;
    const float* row = g_S + (size_t)r * 2048;
    __half* hp = g_P + (size_t)r * 2048;
    int i0 = tid * 4, i1 = i0 + 1024;
    bool h0 = i0 < L, h1 = i1 < L;
    float4 v0 = h0 ? *(const float4*)&row[i0] : make_float4(-1e30f, -1e30f, -1e30f, -1e30f);
    float4 v1 = h1 ? *(const float4*)&row[i1] : make_float4(-1e30f, -1e30f, -1e30f, -1e30f);

    float m = fmaxf(fmaxf(fmaxf(v0.x, v0.y), fmaxf(v0.z, v0.w)),
                    fmaxf(fmaxf(v1.x, v1.y), fmaxf(v1.z, v1.w)));
#pragma unroll
    for (int o = 16; o; o >>= 1) m = fmaxf(m, __shfl_xor_sync(~0u, m, o));
    if ((tid & 31) == 0) red[tid >> 5] = m;
    __syncthreads();
    m = fmaxf(fmaxf(fmaxf(red[0], red[1]), fmaxf(red[2], red[3])),
              fmaxf(fmaxf(red[4], red[5]), fmaxf(red[6], red[7])));

    v0.x = __expf(v0.x - m); v0.y = __expf(v0.y - m);
    v0.z = __expf(v0.z - m); v0.w = __expf(v0.w - m);
    v1.x = __expf(v1.x - m); v1.y = __expf(v1.y - m);
    v1.z = __expf(v1.z - m); v1.w = __expf(v1.w - m);
    float s = v0.x + v0.y + v0.z + v0.w + v1.x + v1.y + v1.z + v1.w;
#pragma unroll
    for (int o = 16; o; o >>= 1) s += __shfl_xor_sync(~0u, s, o);
    __syncthreads();
    if ((tid & 31) == 0) red[tid >> 5] = s;
    __syncthreads();
    s = red[0] + red[1] + red[2] + red[3] + red[4] + red[5] + red[6] + red[7];
    float inv = 1.f / s;

    if (h0) {
        *(__half2*)&hp[i0]     = __floats2half2_rn(v0.x * inv, v0.y * inv);
        *(__half2*)&hp[i0 + 2] = __floats2half2_rn(v0.z * inv, v0.w * inv);
    }
    if (h1) {
        *(__half2*)&hp[i1]     = __floats2half2_rn(v1.x * inv, v1.y * inv);
        *(__half2*)&hp[i1 + 2] = __floats2half2_rn(v1.z * inv, v1.w * inv);
    }
}

// ---------------- pv: 1-pass (P fp16 · V fp16 via ldmatrix.trans) ----------------
__global__ void __launch_bounds__(256, 2) pv_kernel(float* __restrict__ out) {
    extern __shared__ char smem[];
    int tid = threadIdx.x, lane = tid & 31, wid = tid >> 5, wm = wid & 3, wn = wid >> 2;
    uint32_t sb = smem_u32(smem);
    int nt = blockIdx.x * 128, qt = 15 - (int)blockIdx.y, b = blockIdx.z;
    int nch = (qt + 1) * 4;
    const __half* Pb = g_P + ((size_t)b * 2048 + qt * 128) * 2048;
    const __half* Vh = g_Vh + (size_t)b * 2048 * 384 + nt;
    ACC_DECL();

    uint4 rv[4];
    auto ldg = [&](int c) {
#pragma unroll
        for (int i = 0; i < 2; i++) {
            int lin = tid + 256 * i;
            int rr = lin >> 2, cc = (lin & 3) * 8;            // A: 128 x 32
            rv[i * 2 + 0] = *(const uint4*)(Pb + (size_t)rr * 2048 + c * 32 + cc);
            int r2 = lin >> 4, c2 = (lin & 15) * 8;           // B: 32 x 128
            rv[i * 2 + 1] = *(const uint4*)(Vh + (size_t)(c * 32 + r2) * 384 + c2);
        }
    };
    auto stg = [&](char* buf) {
#pragma unroll
        for (int i = 0; i < 2; i++) {
            int lin = tid + 256 * i;
            int rr = lin >> 2, cc = (lin & 3) * 8;
            *(uint4*)(buf + rr * 80 + cc * 2) = rv[i * 2 + 0];
            int r2 = lin >> 4, c2 = (lin & 15) * 8;
            *(uint4*)(buf + 10240 + r2 * 272 + c2 * 2) = rv[i * 2 + 1];
        }
    };
    ldg(0); stg(smem); __syncthreads();

    uint32_t aOff = AOFF(wm, lane);
    uint32_t bOff = (uint32_t)((((lane >> 3) & 1) * 8 + (lane & 7)) * 272 +
                               (wn * 64 + ((lane >> 4) & 1) * 8) * 2);
    for (int c = 0; c < nch; c++) {
        if (c + 1 < nch) ldg(c + 1);
        uint32_t sbase = sb + (uint32_t)(c & 1) * 18944u;
#pragma unroll
        for (int ks = 0; ks < 2; ks++) {
            uint32_t a[2][4], bh[8][2];
#pragma unroll
            for (int mf = 0; mf < 2; mf++) ldsm4(sbase + aOff + mf * 1280 + ks * 32, a[mf]);
#pragma unroll
            for (int n2 = 0; n2 < 4; n2++) {
                uint32_t r[4];
                ldsm4t(sbase + 10240 + bOff + (uint32_t)(ks * 16 * 272 + n2 * 32), r);
                bh[n2 * 2][0] = r[0]; bh[n2 * 2][1] = r[1];
                bh[n2 * 2 + 1][0] = r[2]; bh[n2 * 2 + 1][1] = r[3];
            }
#pragma unroll
            for (int mf = 0; mf < 2; mf++)
#pragma unroll
                for (int nf = 0; nf < 8; nf++) mmah(acc[mf][nf], a[mf], bh[nf]);
        }
        if (c + 1 < nch) stg(smem + (size_t)((c + 1) & 1) * 18944);
        __syncthreads();
    }

    float* Y = out + ((size_t)b * 2048 + qt * 128) * 384 + nt;
#pragma unroll
    for (int mf = 0; mf < 2; mf++)
#pragma unroll
        for (int h = 0; h < 2; h++) {
            int row = wm * 32 + mf * 16 + (lane >> 2) + h * 8;
#pragma unroll
            for (int nf = 0; nf < 8; nf++) {
                float2 v = make_float2(acc[mf][nf][h * 2], acc[mf][nf][h * 2 + 1]);
                *(float2*)&Y[(size_t)row * 384 + wn * 64 + nf * 8 + (lane & 3) * 2] = v;
            }
        }
}

extern "C" void kernel_launch(void* const* d_in, const int* in_sizes, int n_in,
                              void* d_out, int out_size) {
    const float* x  = (const float*)d_in[0];
    const float* Wq = (const float*)d_in[1];
    const float* Wk = (const float*)d_in[2];
    const float* Wv = (const float*)d_in[3];
    float* out = (float*)d_out;
    (void)in_sizes; (void)n_in; (void)out_size;

    cudaFuncSetAttribute(proj_kernel, cudaFuncAttributeMaxDynamicSharedMemorySize, SMEM_GEMM);
    cudaFuncSetAttribute(qk_kernel,   cudaFuncAttributeMaxDynamicSharedMemorySize, SMEM_GEMM);
    cudaFuncSetAttribute(pv_kernel,   cudaFuncAttributeMaxDynamicSharedMemorySize, SMEM_PV);

    wt_kernel<<<dim3(3, 64), 256>>>(Wq, Wk, Wv);
    proj_kernel<<<dim3(3, 256, 3), 256, SMEM_GEMM>>>(x);
    qk_kernel<<<dim3(136, 16), 256, SMEM_GEMM>>>();
    softmax_kernel<<<32768, 256>>>();
    pv_kernel<<<dim3(3, 16, 16), 256, SMEM_PV>>>(out);
}

// round 8
// speedup vs baseline: 8.7242x; 1.0616x over previous
#include <cuda_runtime.h>
#include <cuda_fp16.h>
#include <cstdint>

#define SCALE 0.05103103630798288f   // 384^-0.5
#define SMEM_GEMM 40960               // 2 buf * (A 10240 + B 10240)
#define SMEM_PV   37888               // 2 buf * (A 10240 + B 8704)

__device__ __half g_Qh[16 * 2048 * 384];
__device__ __half g_Kh[16 * 2048 * 384];
__device__ __half g_Vh[16 * 2048 * 384];
__device__ __half g_Pt[16ll * 2048 * 2048];      // P~ = exp(S - m_tile), fp16
__device__ float  g_mt[16 * 16 * 16 * 128];      // per (b,qt,kt,row) tile max
__device__ float  g_lt[16 * 16 * 16 * 128];      // per-tile row sum
__device__ float  g_g [16 * 16 * 16 * 128];      // fold factor exp(m_t-M)/l

__device__ __forceinline__ uint32_t smem_u32(const void* p) {
    uint32_t a;
    asm("{ .reg .u64 t; cvta.to.shared.u64 t, %1; cvt.u32.u64 %0, t; }" : "=r"(a) : "l"(p));
    return a;
}
__device__ __forceinline__ void ldsm4(uint32_t addr, uint32_t* r) {
    asm volatile("ldmatrix.sync.aligned.m8n8.x4.shared.b16 {%0,%1,%2,%3}, [%4];"
        : "=r"(r[0]), "=r"(r[1]), "=r"(r[2]), "=r"(r[3]) : "r"(addr));
}
__device__ __forceinline__ void ldsm4t(uint32_t addr, uint32_t* r) {
    asm volatile("ldmatrix.sync.aligned.m8n8.x4.trans.shared.b16 {%0,%1,%2,%3}, [%4];"
        : "=r"(r[0]), "=r"(r[1]), "=r"(r[2]), "=r"(r[3]) : "r"(addr));
}
__device__ __forceinline__ void mmah(float* c, const uint32_t* a, const uint32_t* b) {
    asm volatile("mma.sync.aligned.m16n8k16.row.col.f32.f16.f16.f32 "
        "{%0,%1,%2,%3}, {%4,%5,%6,%7}, {%8,%9}, {%0,%1,%2,%3};"
        : "+f"(c[0]), "+f"(c[1]), "+f"(c[2]), "+f"(c[3])
        : "r"(a[0]), "r"(a[1]), "r"(a[2]), "r"(a[3]), "r"(b[0]), "r"(b[1]));
}

#define ACC_DECL()                                   \
    float acc[2][8][4];                              \
    _Pragma("unroll") for (int i_ = 0; i_ < 2; i_++) \
    _Pragma("unroll") for (int j_ = 0; j_ < 8; j_++) \
    _Pragma("unroll") for (int q_ = 0; q_ < 4; q_++) acc[i_][j_][q_] = 0.f;

#define AOFF(wm, lane) ((uint32_t)(((wm) * 32 + ((lane) & 15)) * 80 + ((lane) >> 4) * 16))
#define BOFF(wn, lane) ((uint32_t)(((wn) * 64 + (((lane) >> 4) & 1) * 8 + ((lane) & 7)) * 80 + \
                                   (((lane) >> 3) & 1) * 16))
#define BOFFT(wn, lane) ((uint32_t)(((((lane) >> 3) & 1) * 8 + ((lane) & 7)) * 272 + \
                                    ((wn) * 64 + (((lane) >> 4) & 1) * 8) * 2))

// K-major 1-pass chunk: A@0, B@10240; 128 rows x 80B stride
__device__ __forceinline__ void chunk1(uint32_t sbase, uint32_t aOff, uint32_t bOff,
                                       float acc[2][8][4]) {
#pragma unroll
    for (int ks = 0; ks < 2; ks++) {
        uint32_t a[2][4], b[8][2];
#pragma unroll
        for (int mf = 0; mf < 2; mf++) ldsm4(sbase + aOff + mf * 1280 + ks * 32, a[mf]);
#pragma unroll
        for (int n2 = 0; n2 < 4; n2++) {
            uint32_t r[4];
            ldsm4(sbase + 10240 + bOff + n2 * 1280 + ks * 32, r);
            b[n2 * 2][0] = r[0]; b[n2 * 2][1] = r[1];
            b[n2 * 2 + 1][0] = r[2]; b[n2 * 2 + 1][1] = r[3];
        }
#pragma unroll
        for (int mf = 0; mf < 2; mf++)
#pragma unroll
            for (int nf = 0; nf < 8; nf++) mmah(acc[mf][nf], a[mf], b[nf]);
    }
}

// MN-major-B 1-pass chunk: A@0 (80B stride), B@10240 (32 rows x 272B), ldsm.trans
__device__ __forceinline__ void chunk1t(uint32_t sbase, uint32_t aOff, uint32_t bOff,
                                        float acc[2][8][4]) {
#pragma unroll
    for (int ks = 0; ks < 2; ks++) {
        uint32_t a[2][4], b[8][2];
#pragma unroll
        for (int mf = 0; mf < 2; mf++) ldsm4(sbase + aOff + mf * 1280 + ks * 32, a[mf]);
#pragma unroll
        for (int n2 = 0; n2 < 4; n2++) {
            uint32_t r[4];
            ldsm4t(sbase + 10240 + bOff + (uint32_t)(ks * 16 * 272 + n2 * 32), r);
            b[n2 * 2][0] = r[0]; b[n2 * 2][1] = r[1];
            b[n2 * 2 + 1][0] = r[2]; b[n2 * 2 + 1][1] = r[3];
        }
#pragma unroll
        for (int mf = 0; mf < 2; mf++)
#pragma unroll
            for (int nf = 0; nf < 8; nf++) mmah(acc[mf][nf], a[mf], b[nf]);
    }
}

struct __align__(8) hpair { __half2 a, b; };
__device__ __forceinline__ hpair to_h(float4 v) {
    hpair r; r.a = __floats2half2_rn(v.x, v.y); r.b = __floats2half2_rn(v.z, v.w); return r;
}

// ---------------- proj: X(fp32)·W(fp32), both converted to fp16 in-stage ----------------
__global__ void __launch_bounds__(256, 2) proj_kernel(const float* __restrict__ X,
                                                      const float* __restrict__ Wq,
                                                      const float* __restrict__ Wk,
                                                      const float* __restrict__ Wv) {
    extern __shared__ char smem[];
    int tid = threadIdx.x, lane = tid & 31, wid = tid >> 5, wm = wid & 3, wn = wid >> 2;
    uint32_t sb = smem_u32(smem);
    int nt = blockIdx.x * 128, mt = blockIdx.y * 128, z = blockIdx.z;
    const float* gA = X + (size_t)mt * 384;
    const float* gW = ((z == 0) ? Wq : ((z == 1) ? Wk : Wv)) + nt;   // W[k][n], row-major
    ACC_DECL();

    float4 va[4], wb[4];
    auto ldg = [&](int c) {
#pragma unroll
        for (int i = 0; i < 4; i++) {
            int lin = tid + 256 * i, row = lin >> 3, c4 = (lin & 7) * 4;
            va[i] = *(const float4*)(gA + (size_t)row * 384 + c * 32 + c4);
        }
#pragma unroll
        for (int i = 0; i < 2; i++) {
            int lin = tid + 256 * i, r2 = lin >> 4, c2 = (lin & 15) * 8;
            const float* wp = gW + (size_t)(c * 32 + r2) * 384 + c2;
            wb[i * 2 + 0] = *(const float4*)wp;
            wb[i * 2 + 1] = *(const float4*)(wp + 4);
        }
    };
    auto stg = [&](char* buf) {
#pragma unroll
        for (int i = 0; i < 4; i++) {
            int lin = tid + 256 * i, row = lin >> 3, c4 = (lin & 7) * 4;
            *(hpair*)(buf + row * 80 + c4 * 2) = to_h(va[i]);
        }
#pragma unroll
        for (int i = 0; i < 2; i++) {
            int lin = tid + 256 * i, r2 = lin >> 4, c2 = (lin & 15) * 8;
            *(hpair*)(buf + 10240 + r2 * 272 + c2 * 2)     = to_h(wb[i * 2 + 0]);
            *(hpair*)(buf + 10240 + r2 * 272 + c2 * 2 + 8) = to_h(wb[i * 2 + 1]);
        }
    };
    uint32_t aOff = AOFF(wm, lane), bOff = BOFFT(wn, lane);
    ldg(0); stg(smem); __syncthreads();
    for (int c = 0; c < 12; c++) {
        if (c < 11) ldg(c + 1);
        chunk1t(sb + (uint32_t)(c & 1) * 18944u, aOff, bOff, acc);
        if (c < 11) stg(smem + (size_t)((c + 1) & 1) * 18944);
        __syncthreads();
    }

    float s = (z == 0) ? SCALE : 1.f;
    __half* Yh = (z == 0) ? g_Qh : ((z == 1) ? g_Kh : g_Vh);
#pragma unroll
    for (int mf = 0; mf < 2; mf++)
#pragma unroll
        for (int h = 0; h < 2; h++) {
            int row = mt + wm * 32 + mf * 16 + (lane >> 2) + h * 8;
#pragma unroll
            for (int nf = 0; nf < 8; nf++) {
                int col = nt + wn * 64 + nf * 8 + (lane & 3) * 2;
                *(__half2*)&Yh[(size_t)row * 384 + col] =
                    __floats2half2_rn(acc[mf][nf][h * 2] * s, acc[mf][nf][h * 2 + 1] * s);
            }
        }
}

// ---------------- qk: MMA + fused local softmax (P~ fp16 + per-tile row stats) ----------------
__global__ void __launch_bounds__(256, 2) qk_kernel() {
    extern __shared__ char smem[];
    int tid = threadIdx.x, lane = tid & 31, wid = tid >> 5, wm = wid & 3, wn = wid >> 2;
    uint32_t sb = smem_u32(smem);
    int b = blockIdx.y, r_ = blockIdx.x, qt = 0;
    while (r_ > qt) { r_ -= qt + 1; qt++; }
    int kt = r_;
    size_t qb = ((size_t)b * 2048 + qt * 128) * 384;
    size_t kb = ((size_t)b * 2048 + kt * 128) * 384;
    ACC_DECL();

    uint4 rv[4];
    auto ldg = [&](int c) {
#pragma unroll
        for (int i = 0; i < 2; i++) {
            int lin = tid + 256 * i, rr = lin >> 2, cc = (lin & 3) * 8;
            size_t o = (size_t)rr * 384 + c * 32 + cc;
            rv[i * 2 + 0] = *(const uint4*)(g_Qh + qb + o);
            rv[i * 2 + 1] = *(const uint4*)(g_Kh + kb + o);
        }
    };
    auto stg = [&](char* buf) {
#pragma unroll
        for (int i = 0; i < 2; i++) {
            int lin = tid + 256 * i, rr = lin >> 2, cc = (lin & 3) * 8;
            int o = rr * 80 + cc * 2;
            *(uint4*)(buf + o)         = rv[i * 2 + 0];
            *(uint4*)(buf + 10240 + o) = rv[i * 2 + 1];
        }
    };
    uint32_t aOff = AOFF(wm, lane), bOff = BOFF(wn, lane);
    ldg(0); stg(smem); __syncthreads();
    for (int c = 0; c < 12; c++) {
        if (c < 11) ldg(c + 1);
        chunk1(sb + (uint32_t)(c & 1) * 20480u, aOff, bOff, acc);
        if (c < 11) stg(smem + (size_t)((c + 1) & 1) * 20480);
        __syncthreads();
    }

    // ---- fused epilogue: mask, local max, exp, row sums, P~ store ----
    float* sR = (float*)smem;            // [2][128]
    float pm[2][2] = {{-1e30f, -1e30f}, {-1e30f, -1e30f}};
#pragma unroll
    for (int mf = 0; mf < 2; mf++)
#pragma unroll
        for (int nf = 0; nf < 8; nf++)
#pragma unroll
            for (int q = 0; q < 4; q++) {
                int h = q >> 1;
                int qg = qt * 128 + wm * 32 + mf * 16 + (lane >> 2) + h * 8;
                int kg = kt * 128 + wn * 64 + nf * 8 + (lane & 3) * 2 + (q & 1);
                if (kg > qg) acc[mf][nf][q] = -1e30f;
                pm[mf][h] = fmaxf(pm[mf][h], acc[mf][nf][q]);
            }
#pragma unroll
    for (int mf = 0; mf < 2; mf++)
#pragma unroll
        for (int h = 0; h < 2; h++) {
            pm[mf][h] = fmaxf(pm[mf][h], __shfl_xor_sync(~0u, pm[mf][h], 1));
            pm[mf][h] = fmaxf(pm[mf][h], __shfl_xor_sync(~0u, pm[mf][h], 2));
        }
    int rl[2][2];
#pragma unroll
    for (int mf = 0; mf < 2; mf++)
#pragma unroll
        for (int h = 0; h < 2; h++)
            rl[mf][h] = wm * 32 + mf * 16 + (lane >> 2) + h * 8;
    if ((lane & 3) == 0)
#pragma unroll
        for (int mf = 0; mf < 2; mf++)
#pragma unroll
            for (int h = 0; h < 2; h++) sR[wn * 128 + rl[mf][h]] = pm[mf][h];
    __syncthreads();
    float mrow[2][2], ps[2][2] = {{0.f, 0.f}, {0.f, 0.f}};
#pragma unroll
    for (int mf = 0; mf < 2; mf++)
#pragma unroll
        for (int h = 0; h < 2; h++) mrow[mf][h] = fmaxf(sR[rl[mf][h]], sR[128 + rl[mf][h]]);
#pragma unroll
    for (int mf = 0; mf < 2; mf++)
#pragma unroll
        for (int nf = 0; nf < 8; nf++)
#pragma unroll
            for (int q = 0; q < 4; q++) {
                int h = q >> 1;
                float p = __expf(acc[mf][nf][q] - mrow[mf][h]);
                acc[mf][nf][q] = p;
                ps[mf][h] += p;
            }
#pragma unroll
    for (int mf = 0; mf < 2; mf++)
#pragma unroll
        for (int h = 0; h < 2; h++) {
            ps[mf][h] += __shfl_xor_sync(~0u, ps[mf][h], 1);
            ps[mf][h] += __shfl_xor_sync(~0u, ps[mf][h], 2);
        }
    __syncthreads();
    if ((lane & 3) == 0)
#pragma unroll
        for (int mf = 0; mf < 2; mf++)
#pragma unroll
            for (int h = 0; h < 2; h++) sR[wn * 128 + rl[mf][h]] = ps[mf][h];
    __syncthreads();
    size_t statb = ((size_t)(b * 16 + qt) * 16 + kt) * 128;
    if (wn == 0 && (lane & 3) == 0)
#pragma unroll
        for (int mf = 0; mf < 2; mf++)
#pragma unroll
            for (int h = 0; h < 2; h++) {
                g_mt[statb + rl[mf][h]] = mrow[mf][h];
                g_lt[statb + rl[mf][h]] = sR[rl[mf][h]] + sR[128 + rl[mf][h]];
            }
    __half* Prow = g_Pt + ((size_t)b * 2048 + qt * 128) * 2048 + (size_t)kt * 128;
#pragma unroll
    for (int mf = 0; mf < 2; mf++)
#pragma unroll
        for (int h = 0; h < 2; h++) {
#pragma unroll
            for (int nf = 0; nf < 8; nf++) {
                int col = wn * 64 + nf * 8 + (lane & 3) * 2;
                *(__half2*)&Prow[(size_t)rl[mf][h] * 2048 + col] =
                    __floats2half2_rn(acc[mf][nf][h * 2], acc[mf][nf][h * 2 + 1]);
            }
        }
}

// ---------------- norm: fold M and 1/l into per-tile row factors ----------------
__global__ void __launch_bounds__(128) norm_kernel() {
    int bq = blockIdx.x;                // b*16 + qt
    int qt = bq & 15, row = threadIdx.x;
    int ntl = qt + 1;
    size_t base = (size_t)bq * 16 * 128 + row;
    float m = -1e30f;
    for (int t = 0; t < ntl; t++) m = fmaxf(m, g_mt[base + t * 128]);
    float l = 0.f;
    for (int t = 0; t < ntl; t++) l += __expf(g_mt[base + t * 128] - m) * g_lt[base + t * 128];
    float inv = 1.f / l;
    for (int t = 0; t < ntl; t++) g_g[base + t * 128] = __expf(g_mt[base + t * 128] - m) * inv;
}

// ---------------- pv: (g ∘ P~) fp16 · V fp16, g applied during smem stage ----------------
__global__ void __launch_bounds__(256, 2) pv_kernel(float* __restrict__ out) {
    extern __shared__ char smem[];
    int tid = threadIdx.x, lane = tid & 31, wid = tid >> 5, wm = wid & 3, wn = wid >> 2;
    uint32_t sb = smem_u32(smem);
    int nt = blockIdx.x * 128, qt = 15 - (int)blockIdx.y, b = blockIdx.z;
    int nch = (qt + 1) * 4;
    const __half* Pb = g_Pt + ((size_t)b * 2048 + qt * 128) * 2048;
    const __half* Vh = g_Vh + (size_t)b * 2048 * 384 + nt;
    const size_t statb = (size_t)(b * 16 + qt) * 16 * 128;
    ACC_DECL();

    uint4 rv[4];
    float gf[2];
    auto ldg = [&](int c) {
        int t = c >> 2;
#pragma unroll
        for (int i = 0; i < 2; i++) {
            int lin = tid + 256 * i;
            int rr = lin >> 2, cc = (lin & 3) * 8;            // A: 128 x 32
            rv[i * 2 + 0] = *(const uint4*)(Pb + (size_t)rr * 2048 + c * 32 + cc);
            gf[i] = g_g[statb + (size_t)t * 128 + rr];
            int r2 = lin >> 4, c2 = (lin & 15) * 8;           // B: 32 x 128
            rv[i * 2 + 1] = *(const uint4*)(Vh + (size_t)(c * 32 + r2) * 384 + c2);
        }
    };
    auto stg = [&](char* buf) {
#pragma unroll
        for (int i = 0; i < 2; i++) {
            int lin = tid + 256 * i;
            int rr = lin >> 2, cc = (lin & 3) * 8;
            __half2* ph = (__half2*)&rv[i * 2 + 0];
            float g = gf[i];
#pragma unroll
            for (int j = 0; j < 4; j++) {
                float2 f = __half22float2(ph[j]);
                ph[j] = __floats2half2_rn(f.x * g, f.y * g);
            }
            *(uint4*)(buf + rr * 80 + cc * 2) = rv[i * 2 + 0];
            int r2 = lin >> 4, c2 = (lin & 15) * 8;
            *(uint4*)(buf + 10240 + r2 * 272 + c2 * 2) = rv[i * 2 + 1];
        }
    };
    ldg(0); stg(smem); __syncthreads();

    uint32_t aOff = AOFF(wm, lane), bOff = BOFFT(wn, lane);
    for (int c = 0; c < nch; c++) {
        if (c + 1 < nch) ldg(c + 1);
        chunk1t(sb + (uint32_t)(c & 1) * 18944u, aOff, bOff, acc);
        if (c + 1 < nch) stg(smem + (size_t)((c + 1) & 1) * 18944);
        __syncthreads();
    }

    float* Y = out + ((size_t)b * 2048 + qt * 128) * 384 + nt;
#pragma unroll
    for (int mf = 0; mf < 2; mf++)
#pragma unroll
        for (int h = 0; h < 2; h++) {
            int row = wm * 32 + mf * 16 + (lane >> 2) + h * 8;
#pragma unroll
            for (int nf = 0; nf < 8; nf++) {
                float2 v = make_float2(acc[mf][nf][h * 2], acc[mf][nf][h * 2 + 1]);
                *(float2*)&Y[(size_t)row * 384 + wn * 64 + nf * 8 + (lane & 3) * 2] = v;
            }
        }
}

extern "C" void kernel_launch(void* const* d_in, const int* in_sizes, int n_in,
                              void* d_out, int out_size) {
    const float* x  = (const float*)d_in[0];
    const float* Wq = (const float*)d_in[1];
    const float* Wk = (const float*)d_in[2];
    const float* Wv = (const float*)d_in[3];
    float* out = (float*)d_out;
    (void)in_sizes; (void)n_in; (void)out_size;

    cudaFuncSetAttribute(proj_kernel, cudaFuncAttributeMaxDynamicSharedMemorySize, SMEM_PV);
    cudaFuncSetAttribute(qk_kernel,   cudaFuncAttributeMaxDynamicSharedMemorySize, SMEM_GEMM);
    cudaFuncSetAttribute(pv_kernel,   cudaFuncAttributeMaxDynamicSharedMemorySize, SMEM_PV);

    proj_kernel<<<dim3(3, 256, 3), 256, SMEM_PV>>>(x, Wq, Wk, Wv);
    qk_kernel<<<dim3(136, 16), 256, SMEM_GEMM>>>();
    norm_kernel<<<256, 128>>>();
    pv_kernel<<<dim3(3, 16, 16), 256, SMEM_PV>>>(out);
}